// round 7
// baseline (speedup 1.0000x reference)
#include <cuda_runtime.h>
#include <math.h>

#define B 64
#define S 512
#define H 512
#define IN 84
#define NC 100
#define XW 266

#define NGRP 4
#define GCTA 32          // CTAs per group
#define BPG 16           // batches per group
#define UPC 16           // hidden units per CTA
#define ROWS 64          // gate rows per CTA (4 gates x 16 units)
#define NCTA (NGRP * GCTA)
#define NTH 256

// ---- static device scratch ----
__device__ float g_feats[S * NGRP * IN * BPG];       // [S][grp][IN][16]
__device__ float g_hbuf2[2 * NGRP * H * BPG];        // [par][grp][H][16]
__device__ float g_lstm[(size_t)S * H * B];          // [S][H][B]
__device__ float g_sc[S * B];
__device__ float g_ctx[H * B];
__device__ unsigned g_ctrs[64];                      // grp uses [grp*16]

// ---- SMEM layout (float offsets) ----
#define OFF_H    0                            // h    [512][16]   8192
#define OFF_F    (OFF_H + 512 * BPG)          // f    [84][16]    1344
#define OFF_WH   (OFF_F + IN * BPG)           // WhT  [512][64]   32768
#define OFF_WI   (OFF_WH + 512 * ROWS)        // WiT  [84][64]    5376
#define OFF_RED  (OFF_WI + IN * ROWS)         // red  [8][16][66] 8448
#define OFF_BIAS (OFF_RED + 8 * BPG * 66)     // [64]
#define OFF_END  (OFF_BIAS + ROWS)
#define OFF_MBAR_B (OFF_END * 4)
#define NMBAR 17
#define SMEM_BYTES (OFF_MBAR_B + NMBAR * 8)

// ---- packed fp32x2 helpers ----
__device__ __forceinline__ unsigned long long bcast2(float x) {
    unsigned long long r;
    unsigned u = __float_as_uint(x);
    asm("mov.b64 %0, {%1, %1};" : "=l"(r) : "r"(u));
    return r;
}
__device__ __forceinline__ void ffma2(unsigned long long& d,
                                      unsigned long long a,
                                      unsigned long long b) {
    asm("fma.rn.f32x2 %0, %1, %2, %0;" : "+l"(d) : "l"(a), "l"(b));
}
__device__ __forceinline__ float sigf(float x) {
    return __fdividef(1.0f, 1.0f + __expf(-x));
}
__device__ __forceinline__ float tanhfast(float x) {
    return __fdividef(2.0f, 1.0f + __expf(-2.0f * x)) - 1.0f;
}

// ---- mbarrier / bulk-copy helpers ----
__device__ __forceinline__ unsigned smem_u32(const void* p) {
    return (unsigned)__cvta_generic_to_shared(p);
}
__device__ __forceinline__ void mbar_init(unsigned a, unsigned cnt) {
    asm volatile("mbarrier.init.shared.b64 [%0], %1;" :: "r"(a), "r"(cnt) : "memory");
}
__device__ __forceinline__ void mbar_expect(unsigned a, unsigned bytes) {
    asm volatile("mbarrier.arrive.expect_tx.shared.b64 _, [%0], %1;"
                 :: "r"(a), "r"(bytes) : "memory");
}
__device__ __forceinline__ void bulk_g2s(unsigned dst, const void* src,
                                         unsigned bytes, unsigned mbar) {
    asm volatile(
        "cp.async.bulk.shared::cluster.global.mbarrier::complete_tx::bytes "
        "[%0], [%1], %2, [%3];"
        :: "r"(dst), "l"(src), "r"(bytes), "r"(mbar) : "memory");
}
__device__ __forceinline__ void mbar_wait(unsigned a, unsigned parity) {
    asm volatile(
        "{\n\t.reg .pred P;\n\t"
        "W%=:\n\t"
        "mbarrier.try_wait.parity.shared.b64 P, [%0], %1, 0x989680;\n\t"
        "@P bra D%=;\n\t"
        "bra W%=;\n\t"
        "D%=:\n\t}"
        :: "r"(a), "r"(parity) : "memory");
}
__device__ __forceinline__ unsigned elect_one() {
    unsigned pred;
    asm volatile(
        "{\n\t.reg .pred p;\n\t"
        "elect.sync _|p, 0xFFFFFFFF;\n\t"
        "selp.b32 %0, 1, 0, p;\n\t}"
        : "=r"(pred));
    return pred;
}

// ============================================================ reset
__global__ void reset_kernel() {
    int t = blockIdx.x * blockDim.x + threadIdx.x;
    if (t < 64) g_ctrs[t] = 0u;
    if (t < 2 * NGRP * H * BPG) g_hbuf2[t] = 0.0f;
}

// ============================================================ preprocessing
__global__ void prep_kernel(const float* __restrict__ x) {
    int s = blockIdx.x;
    int b = threadIdx.x;
    int grp = b >> 4, bl = b & 15;
    float* fdst = g_feats + ((size_t)s * NGRP + grp) * IN * BPG + bl;
    const float* xp = x + ((size_t)b * S + s) * XW;
    float cx = xp[0], cy = xp[1];
    #pragma unroll
    for (int hnd = 0; hnd < 2; hnd++) {
        int pbase = (hnd == 0) ? 91 : 112;
        float mnx = 1e30f, mxx = -1e30f, mny = 1e30f, mxy = -1e30f;
        #pragma unroll
        for (int p = 0; p < 21; p++) {
            float px = xp[(pbase + p) * 2];
            float py = xp[(pbase + p) * 2 + 1];
            mnx = fminf(mnx, px); mxx = fmaxf(mxx, px);
            mny = fminf(mny, py); mxy = fmaxf(mxy, py);
        }
        float whx = mxx - mnx, why = mxy - mny;
        bool ok = (whx != 0.0f) && (why != 0.0f);
        float sx = ok ? whx : 1.0f;
        float sy = ok ? why : 1.0f;
        #pragma unroll
        for (int p = 0; p < 21; p++) {
            float px = xp[(pbase + p) * 2];
            float py = xp[(pbase + p) * 2 + 1];
            int i0 = hnd * 42 + p * 2;
            fdst[i0 * BPG]       = (px - cx) / sx;
            fdst[(i0 + 1) * BPG] = (py - cy) / sy;
        }
    }
}

// ============================================================ recurrence
// CTA: grp = blk>>5 (16 batches), cg = blk&31 (16 units -> 64 gate rows)
// 8 warps = K chunks of 64. lane: rg = lane>>2 (8 rows), bg = lane&3 (4 b)
#define STEP_K(hv, wa, wb) do {                                   \
    unsigned long long hb0 = bcast2(hv.x);                        \
    unsigned long long hb1 = bcast2(hv.y);                        \
    unsigned long long hb2 = bcast2(hv.z);                        \
    unsigned long long hb3 = bcast2(hv.w);                        \
    ffma2(acc[0],  wa.x, hb0); ffma2(acc[1],  wa.x, hb1);         \
    ffma2(acc[2],  wa.x, hb2); ffma2(acc[3],  wa.x, hb3);         \
    ffma2(acc[4],  wa.y, hb0); ffma2(acc[5],  wa.y, hb1);         \
    ffma2(acc[6],  wa.y, hb2); ffma2(acc[7],  wa.y, hb3);         \
    ffma2(acc[8],  wb.x, hb0); ffma2(acc[9],  wb.x, hb1);         \
    ffma2(acc[10], wb.x, hb2); ffma2(acc[11], wb.x, hb3);         \
    ffma2(acc[12], wb.y, hb0); ffma2(acc[13], wb.y, hb1);         \
    ffma2(acc[14], wb.y, hb2); ffma2(acc[15], wb.y, hb3);         \
} while (0)

__global__ void __launch_bounds__(NTH, 1)
lstm_kernel(const float* __restrict__ W_ih, const float* __restrict__ W_hh,
            const float* __restrict__ b_ih, const float* __restrict__ b_hh) {
    extern __shared__ float sm[];
    float* h_sm = sm + OFF_H;
    float* f_sm = sm + OFF_F;
    float* Wh_t = sm + OFF_WH;
    float* Wi_t = sm + OFF_WI;
    float* red  = sm + OFF_RED;
    float* bias = sm + OFF_BIAS;

    const int t    = threadIdx.x;
    const int blk  = blockIdx.x;
    const int grp  = blk >> 5;
    const int cg   = blk & 31;
    const int lane = t & 31;
    const int kp   = t >> 5;       // warp = K chunk of 64
    const int rg   = lane >> 2;    // 0..7  (8 rows each)
    const int bg   = lane & 3;     // 0..3  (4 batches each)

    const unsigned smem_base = smem_u32(sm);
    const unsigned mbar0 = smem_base + OFF_MBAR_B;
    const unsigned h_dst = smem_base + OFF_H * 4;
    const unsigned f_dst = smem_base + OFF_F * 4;

    // ---- one-time weight staging: WhT[k][64 rows], row = gate*16 + ul ----
    for (int idx = t; idx < ROWS * H; idx += NTH) {
        int r = idx & 63, k = idx >> 6;
        int grow = (r >> 4) * H + cg * UPC + (r & 15);
        Wh_t[k * 64 + r] = W_hh[(size_t)grow * H + k];
    }
    for (int idx = t; idx < ROWS * IN; idx += NTH) {
        int r = idx & 63, k = idx >> 6;
        int grow = (r >> 4) * H + cg * UPC + (r & 15);
        Wi_t[k * 64 + r] = W_ih[(size_t)grow * IN + k];
    }
    if (t < ROWS) {
        int grow = (t >> 4) * H + cg * UPC + (t & 15);
        bias[t] = b_ih[grow] + b_hh[grow];
    }
    if (t == 0) {
        #pragma unroll
        for (int i = 0; i < NMBAR; i++) mbar_init(mbar0 + i * 8, 1);
    }
    __syncthreads();

    // feats K slice for this warp
    const int foff = kp * 10 + (kp < 4 ? kp : 4);
    const int fcnt = (kp < 4) ? 11 : 10;

    // gate-phase mapping: thread = (unit ul, batch b)
    const int ul = t >> 4;          // 0..15
    const int gb = t & 15;          // 0..15
    const int u_glob = cg * UPC + ul;
    float creg = 0.0f;

    const unsigned isleader = elect_one();
    unsigned* my_ctr = &g_ctrs[grp * 16];
    const float* hsrc_grp = g_hbuf2 + (size_t)grp * H * BPG;
    const float* fsrc_grp = g_feats + (size_t)grp * IN * BPG;

    for (int s = 0; s < S; s++) {
        const int cur = s & 1, nxt = cur ^ 1;
        const unsigned par = (unsigned)(s & 1);

        // ---- per-warp leader issues its own copies ----
        if (isleader) {
            asm volatile("fence.proxy.async;" ::: "memory");
            if (kp == 7) {
                mbar_expect(mbar0 + 16 * 8, IN * BPG * 4u);
                bulk_g2s(f_dst, fsrc_grp + (size_t)s * NGRP * IN * BPG,
                         IN * BPG * 4u, mbar0 + 16 * 8);
            }
            const float* hsrc = hsrc_grp + cur * NGRP * H * BPG + kp * 64 * BPG;
            mbar_expect(mbar0 + (2 * kp) * 8, 2048u);
            bulk_g2s(h_dst + kp * 4096u, hsrc, 2048u, mbar0 + (2 * kp) * 8);
            mbar_expect(mbar0 + (2 * kp + 1) * 8, 2048u);
            bulk_g2s(h_dst + kp * 4096u + 2048u, hsrc + 512, 2048u,
                     mbar0 + (2 * kp + 1) * 8);
        }

        unsigned long long acc[16];
        #pragma unroll
        for (int i = 0; i < 16; i++) acc[i] = 0ull;

        // ---- input projection FIRST (feats land fast; h gets headroom) ----
        mbar_wait(mbar0 + 16 * 8, par);
        {
            #pragma unroll 2
            for (int k = foff; k < foff + fcnt; k++) {
                float4 hv = *(const float4*)(f_sm + k * BPG + bg * 4);
                ulonglong2 wa = *(const ulonglong2*)(Wi_t + k * 64 + rg * 8);
                ulonglong2 wb = *(const ulonglong2*)(Wi_t + k * 64 + rg * 8 + 4);
                STEP_K(hv, wa, wb);
            }
        }
        // ---- h-GEMM half 0: k in [kp*64, kp*64+32) ----
        mbar_wait(mbar0 + (2 * kp) * 8, par);
        {
            const int k0 = kp * 64;
            #pragma unroll 8
            for (int k = k0; k < k0 + 32; k++) {
                float4 hv = *(const float4*)(h_sm + k * BPG + bg * 4);
                ulonglong2 wa = *(const ulonglong2*)(Wh_t + k * 64 + rg * 8);
                ulonglong2 wb = *(const ulonglong2*)(Wh_t + k * 64 + rg * 8 + 4);
                STEP_K(hv, wa, wb);
            }
        }
        // ---- half 1 ----
        mbar_wait(mbar0 + (2 * kp + 1) * 8, par);
        {
            const int k0 = kp * 64 + 32;
            #pragma unroll 8
            for (int k = k0; k < k0 + 32; k++) {
                float4 hv = *(const float4*)(h_sm + k * BPG + bg * 4);
                ulonglong2 wa = *(const ulonglong2*)(Wh_t + k * 64 + rg * 8);
                ulonglong2 wb = *(const ulonglong2*)(Wh_t + k * 64 + rg * 8 + 4);
                STEP_K(hv, wa, wb);
            }
        }

        // ---- partials: red[kp][16 b][66 r-pad], u64 row-pair stores ----
        {
            float* rp0 = red + (kp * BPG + bg * 4) * 66 + rg * 8;
            #pragma unroll
            for (int rp = 0; rp < 4; rp++) {
                #pragma unroll
                for (int j = 0; j < 4; j++) {
                    *(unsigned long long*)(rp0 + j * 66 + rp * 2) = acc[rp * 4 + j];
                }
            }
        }
        __syncthreads();

        // ---- reduce + gates: thread = (unit ul, batch gb) ----
        {
            float g4[4];
            #pragma unroll
            for (int gt = 0; gt < 4; gt++) {
                int r = gt * UPC + ul;
                float v = bias[r];
                #pragma unroll
                for (int p = 0; p < 8; p++)
                    v += red[(p * BPG + gb) * 66 + r];
                g4[gt] = v;
            }
            float i_ = sigf(g4[0]);
            float f_ = sigf(g4[1]);
            float gg = tanhfast(g4[2]);
            float o_ = sigf(g4[3]);
            creg = f_ * creg + i_ * gg;
            float hn = o_ * tanhfast(creg);
            g_hbuf2[(size_t)(nxt * NGRP + grp) * H * BPG + u_glob * BPG + gb] = hn;
            g_lstm[((size_t)s * H + u_glob) * B + grp * BPG + gb] = hn;
        }

        // ---- group barrier (32 CTAs, own counter) ----
        if (s != S - 1) {
            __syncthreads();
            if (t == 0) {
                __threadfence();
                atomicAdd(my_ctr, 1u);
                unsigned target = (unsigned)(s + 1) * GCTA;
                unsigned v;
                do {
                    asm volatile("ld.acquire.gpu.u32 %0, [%1];"
                                 : "=r"(v) : "l"(my_ctr) : "memory");
                } while (v < target);
            }
            __syncthreads();
        }
    }
}

// ============================================================ attention
__global__ void __launch_bounds__(256)
scores_kernel(const float* __restrict__ attn_w) {
    __shared__ float aw[H];
    __shared__ float part[4 * 64];
    int t = threadIdx.x, s = blockIdx.x;
    int st = t >> 6, b = t & 63;
    for (int i = t; i < H; i += 256) aw[i] = attn_w[i];
    __syncthreads();
    const float* Ls = g_lstm + (size_t)s * H * B;
    float acc = 0.0f;
    #pragma unroll 8
    for (int h = st * 128; h < st * 128 + 128; h++)
        acc = fmaf(aw[h], Ls[h * B + b], acc);
    part[st * 64 + b] = acc;
    __syncthreads();
    if (st == 0)
        g_sc[s * B + b] = part[b] + part[64 + b] + part[128 + b] + part[192 + b];
}

__global__ void __launch_bounds__(256)
softmax_kernel(float* __restrict__ out) {
    __shared__ float s_red[8];
    int b = blockIdx.x, t = threadIdx.x;
    int lane = t & 31, warp = t >> 5;
    float v[2];
    v[0] = g_sc[t * B + b];
    v[1] = g_sc[(t + 256) * B + b];
    float m = fmaxf(v[0], v[1]);
    #pragma unroll
    for (int o = 16; o; o >>= 1) m = fmaxf(m, __shfl_xor_sync(~0u, m, o));
    if (lane == 0) s_red[warp] = m;
    __syncthreads();
    m = s_red[0];
    #pragma unroll
    for (int i = 1; i < 8; i++) m = fmaxf(m, s_red[i]);
    __syncthreads();
    float e0 = expf(v[0] - m), e1 = expf(v[1] - m);
    float sum = e0 + e1;
    #pragma unroll
    for (int o = 16; o; o >>= 1) sum += __shfl_xor_sync(~0u, sum, o);
    if (lane == 0) s_red[warp] = sum;
    __syncthreads();
    float tot = 0.0f;
    #pragma unroll
    for (int i = 0; i < 8; i++) tot += s_red[i];
    float inv = 1.0f / tot;
    float w0 = e0 * inv, w1 = e1 * inv;
    g_sc[t * B + b] = w0;
    g_sc[(t + 256) * B + b] = w1;
    out[NC * B + b * S + t] = w0;
    out[NC * B + b * S + t + 256] = w1;
}

__global__ void __launch_bounds__(256)
ctx_kernel() {
    __shared__ float part[4 * 64];
    int t = threadIdx.x, h = blockIdx.x;
    int st = t >> 6, b = t & 63;
    float acc = 0.0f;
    const float* Lb = g_lstm + (size_t)h * B + b;
    #pragma unroll 8
    for (int s = st * 128; s < st * 128 + 128; s++)
        acc = fmaf(g_sc[s * B + b], Lb[(size_t)s * H * B], acc);
    part[st * 64 + b] = acc;
    __syncthreads();
    if (st == 0)
        g_ctx[h * B + b] = part[b] + part[64 + b] + part[128 + b] + part[192 + b];
}

__global__ void __launch_bounds__(64)
fc_kernel(const float* __restrict__ fc_w, const float* __restrict__ fc_b,
          float* __restrict__ out) {
    __shared__ float wrow[H];
    int c = blockIdx.x, b = threadIdx.x;
    for (int i = b; i < H; i += 64) wrow[i] = fc_w[(size_t)c * H + i];
    __syncthreads();
    float acc = fc_b[c];
    #pragma unroll 8
    for (int h = 0; h < H; h++)
        acc = fmaf(wrow[h], g_ctx[h * B + b], acc);
    out[b * NC + c] = acc;
}

// ============================================================ launch
extern "C" void kernel_launch(void* const* d_in, const int* in_sizes, int n_in,
                              void* d_out, int out_size) {
    const float* x      = (const float*)d_in[0];
    const float* W_ih   = (const float*)d_in[1];
    const float* W_hh   = (const float*)d_in[2];
    const float* b_ih   = (const float*)d_in[3];
    const float* b_hh   = (const float*)d_in[4];
    const float* attn_w = (const float*)d_in[5];
    const float* fc_w   = (const float*)d_in[6];
    const float* fc_b   = (const float*)d_in[7];
    float* out = (float*)d_out;

    cudaFuncSetAttribute(lstm_kernel,
                         cudaFuncAttributeMaxDynamicSharedMemorySize, SMEM_BYTES);

    reset_kernel<<<(2 * NGRP * H * BPG + NTH - 1) / NTH, NTH>>>();
    prep_kernel<<<S, B>>>(x);
    lstm_kernel<<<NCTA, NTH, SMEM_BYTES>>>(W_ih, W_hh, b_ih, b_hh);
    scores_kernel<<<S, 256>>>(attn_w);
    softmax_kernel<<<B, 256>>>(out);
    ctx_kernel<<<H, 256>>>();
    fc_kernel<<<NC, 64>>>(fc_w, fc_b, out);
}

// round 8
// speedup vs baseline: 1.0552x; 1.0552x over previous
#include <cuda_runtime.h>
#include <math.h>

#define B 64
#define S 512
#define H 512
#define IN 84
#define NC 100
#define XW 266

#define NGRP 4
#define GCTA 32          // CTAs per group
#define BPG 16           // batches per group
#define UPC 16           // hidden units per CTA
#define ROWS 64          // gate rows per CTA (4 gates x 16 units)
#define NCTA (NGRP * GCTA)
#define NTH 256

#define FBYTES (IN * BPG * 4)     // 5376 B feats slice

// ---- static device scratch ----
__device__ float g_feats[S * NGRP * IN * BPG];       // [S][grp][IN][16]
__device__ float g_hbuf2[2 * NGRP * H * BPG];        // [par][grp][H][16]
__device__ float g_lstm[(size_t)S * H * B];          // [S][H][B]
__device__ float g_sc[S * B];
__device__ float g_ctx[H * B];
__device__ unsigned g_ctrs[64];                      // grp uses [grp*16]

// ---- SMEM layout (float offsets) ----
#define OFF_H    0                            // h    [512][16]       8192
#define OFF_F    (OFF_H + 512 * BPG)          // f    [2][84][16]     2688
#define OFF_WH   (OFF_F + 2 * IN * BPG)       // WhT  [512][64]       32768
#define OFF_WI   (OFF_WH + 512 * ROWS)        // WiT  [84][64]        5376
#define OFF_RED  (OFF_WI + IN * ROWS)         // red  [8][16][66]     8448
#define OFF_BIAS (OFF_RED + 8 * BPG * 66)     // [64]
#define OFF_END  (OFF_BIAS + ROWS)
#define OFF_MBAR_B (OFF_END * 4)
#define NMBAR 18                              // 16 h + 2 feats
#define SMEM_BYTES (OFF_MBAR_B + NMBAR * 8)

// ---- packed fp32x2 helpers ----
__device__ __forceinline__ unsigned long long bcast2(float x) {
    unsigned long long r;
    unsigned u = __float_as_uint(x);
    asm("mov.b64 %0, {%1, %1};" : "=l"(r) : "r"(u));
    return r;
}
__device__ __forceinline__ void ffma2(unsigned long long& d,
                                      unsigned long long a,
                                      unsigned long long b) {
    asm("fma.rn.f32x2 %0, %1, %2, %0;" : "+l"(d) : "l"(a), "l"(b));
}
__device__ __forceinline__ float sigf(float x) {
    return __fdividef(1.0f, 1.0f + __expf(-x));
}
__device__ __forceinline__ float tanhfast(float x) {
    return __fdividef(2.0f, 1.0f + __expf(-2.0f * x)) - 1.0f;
}

// ---- mbarrier / bulk-copy helpers ----
__device__ __forceinline__ unsigned smem_u32(const void* p) {
    return (unsigned)__cvta_generic_to_shared(p);
}
__device__ __forceinline__ void mbar_init(unsigned a, unsigned cnt) {
    asm volatile("mbarrier.init.shared.b64 [%0], %1;" :: "r"(a), "r"(cnt) : "memory");
}
__device__ __forceinline__ void mbar_expect(unsigned a, unsigned bytes) {
    asm volatile("mbarrier.arrive.expect_tx.shared.b64 _, [%0], %1;"
                 :: "r"(a), "r"(bytes) : "memory");
}
__device__ __forceinline__ void bulk_g2s(unsigned dst, const void* src,
                                         unsigned bytes, unsigned mbar) {
    asm volatile(
        "cp.async.bulk.shared::cluster.global.mbarrier::complete_tx::bytes "
        "[%0], [%1], %2, [%3];"
        :: "r"(dst), "l"(src), "r"(bytes), "r"(mbar) : "memory");
}
__device__ __forceinline__ void mbar_wait(unsigned a, unsigned parity) {
    asm volatile(
        "{\n\t.reg .pred P;\n\t"
        "W%=:\n\t"
        "mbarrier.try_wait.parity.shared.b64 P, [%0], %1, 0x989680;\n\t"
        "@P bra D%=;\n\t"
        "bra W%=;\n\t"
        "D%=:\n\t}"
        :: "r"(a), "r"(parity) : "memory");
}
__device__ __forceinline__ unsigned elect_one() {
    unsigned pred;
    asm volatile(
        "{\n\t.reg .pred p;\n\t"
        "elect.sync _|p, 0xFFFFFFFF;\n\t"
        "selp.b32 %0, 1, 0, p;\n\t}"
        : "=r"(pred));
    return pred;
}

// ============================================================ reset
__global__ void reset_kernel() {
    int t = blockIdx.x * blockDim.x + threadIdx.x;
    if (t < 64) g_ctrs[t] = 0u;
    if (t < 2 * NGRP * H * BPG) g_hbuf2[t] = 0.0f;
}

// ============================================================ preprocessing
__global__ void prep_kernel(const float* __restrict__ x) {
    int s = blockIdx.x;
    int b = threadIdx.x;
    int grp = b >> 4, bl = b & 15;
    float* fdst = g_feats + ((size_t)s * NGRP + grp) * IN * BPG + bl;
    const float* xp = x + ((size_t)b * S + s) * XW;
    float cx = xp[0], cy = xp[1];
    #pragma unroll
    for (int hnd = 0; hnd < 2; hnd++) {
        int pbase = (hnd == 0) ? 91 : 112;
        float mnx = 1e30f, mxx = -1e30f, mny = 1e30f, mxy = -1e30f;
        #pragma unroll
        for (int p = 0; p < 21; p++) {
            float px = xp[(pbase + p) * 2];
            float py = xp[(pbase + p) * 2 + 1];
            mnx = fminf(mnx, px); mxx = fmaxf(mxx, px);
            mny = fminf(mny, py); mxy = fmaxf(mxy, py);
        }
        float whx = mxx - mnx, why = mxy - mny;
        bool ok = (whx != 0.0f) && (why != 0.0f);
        float sx = ok ? whx : 1.0f;
        float sy = ok ? why : 1.0f;
        #pragma unroll
        for (int p = 0; p < 21; p++) {
            float px = xp[(pbase + p) * 2];
            float py = xp[(pbase + p) * 2 + 1];
            int i0 = hnd * 42 + p * 2;
            fdst[i0 * BPG]       = (px - cx) / sx;
            fdst[(i0 + 1) * BPG] = (py - cy) / sy;
        }
    }
}

// ============================================================ recurrence
#define STEP_K(hv, wa, wb) do {                                   \
    unsigned long long hb0 = bcast2(hv.x);                        \
    unsigned long long hb1 = bcast2(hv.y);                        \
    unsigned long long hb2 = bcast2(hv.z);                        \
    unsigned long long hb3 = bcast2(hv.w);                        \
    ffma2(acc[0],  wa.x, hb0); ffma2(acc[1],  wa.x, hb1);         \
    ffma2(acc[2],  wa.x, hb2); ffma2(acc[3],  wa.x, hb3);         \
    ffma2(acc[4],  wa.y, hb0); ffma2(acc[5],  wa.y, hb1);         \
    ffma2(acc[6],  wa.y, hb2); ffma2(acc[7],  wa.y, hb3);         \
    ffma2(acc[8],  wb.x, hb0); ffma2(acc[9],  wb.x, hb1);         \
    ffma2(acc[10], wb.x, hb2); ffma2(acc[11], wb.x, hb3);         \
    ffma2(acc[12], wb.y, hb0); ffma2(acc[13], wb.y, hb1);         \
    ffma2(acc[14], wb.y, hb2); ffma2(acc[15], wb.y, hb3);         \
} while (0)

__global__ void __launch_bounds__(NTH, 1)
lstm_kernel(const float* __restrict__ W_ih, const float* __restrict__ W_hh,
            const float* __restrict__ b_ih, const float* __restrict__ b_hh) {
    extern __shared__ float sm[];
    float* h_sm = sm + OFF_H;
    float* Wh_t = sm + OFF_WH;
    float* Wi_t = sm + OFF_WI;
    float* red  = sm + OFF_RED;
    float* bias = sm + OFF_BIAS;

    const int t    = threadIdx.x;
    const int blk  = blockIdx.x;
    const int grp  = blk >> 5;
    const int cg   = blk & 31;
    const int lane = t & 31;
    const int kp   = t >> 5;       // warp = K chunk of 64
    const int rg   = lane >> 2;    // 0..7  (8 rows each)
    const int bg   = lane & 3;     // 0..3  (4 batches each)

    const unsigned smem_base = smem_u32(sm);
    const unsigned mbar0 = smem_base + OFF_MBAR_B;          // 16 h mbars
    const unsigned mbarf = mbar0 + 16 * 8;                  // 2 feats mbars
    const unsigned h_dst = smem_base + OFF_H * 4;
    const unsigned f_dst = smem_base + OFF_F * 4;

    // ---- one-time weight staging: WhT[k][64 rows], row = gate*16 + ul ----
    for (int idx = t; idx < ROWS * H; idx += NTH) {
        int r = idx & 63, k = idx >> 6;
        int grow = (r >> 4) * H + cg * UPC + (r & 15);
        Wh_t[k * 64 + r] = W_hh[(size_t)grow * H + k];
    }
    for (int idx = t; idx < ROWS * IN; idx += NTH) {
        int r = idx & 63, k = idx >> 6;
        int grow = (r >> 4) * H + cg * UPC + (r & 15);
        Wi_t[k * 64 + r] = W_ih[(size_t)grow * IN + k];
    }
    if (t < ROWS) {
        int grow = (t >> 4) * H + cg * UPC + (t & 15);
        bias[t] = b_ih[grow] + b_hh[grow];
    }
    if (t == 0) {
        #pragma unroll
        for (int i = 0; i < NMBAR; i++) mbar_init(mbar0 + i * 8, 1);
    }
    __syncthreads();

    const float* fsrc_grp = g_feats + (size_t)grp * IN * BPG;
    const float* hsrc_grp = g_hbuf2 + (size_t)grp * H * BPG;
    unsigned* my_ctr = &g_ctrs[grp * 16];

    // feats K slice for this warp
    const int foff = kp * 10 + (kp < 4 ? kp : 4);
    const int fcnt = (kp < 4) ? 11 : 10;

    // gate-phase mapping: thread = (unit ul, batch gb)
    const int ul = t >> 4;
    const int gb = t & 15;
    const int u_glob = cg * UPC + ul;
    float creg = 0.0f;

    const unsigned isleader = elect_one();

    // ---- prefetch feats for s=0 into buffer 0 ----
    if (kp == 7 && isleader) {
        asm volatile("fence.proxy.async;" ::: "memory");
        mbar_expect(mbarf, FBYTES);
        bulk_g2s(f_dst, fsrc_grp, FBYTES, mbarf);
    }

    for (int s = 0; s < S; s++) {
        const int cur = s & 1, nxt = cur ^ 1;
        const unsigned par = (unsigned)(s & 1);
        const int fb = s & 1;
        const unsigned fpar = (unsigned)((s >> 1) & 1);

        // ---- per-warp leader: issue h copies; kp7 also prefetches feats s+1 ----
        if (isleader) {
            asm volatile("fence.proxy.async;" ::: "memory");
            const float* hsrc = hsrc_grp + cur * NGRP * H * BPG + kp * 64 * BPG;
            mbar_expect(mbar0 + (2 * kp) * 8, 2048u);
            bulk_g2s(h_dst + kp * 4096u, hsrc, 2048u, mbar0 + (2 * kp) * 8);
            mbar_expect(mbar0 + (2 * kp + 1) * 8, 2048u);
            bulk_g2s(h_dst + kp * 4096u + 2048u, hsrc + 512, 2048u,
                     mbar0 + (2 * kp + 1) * 8);
            if (kp == 7 && s + 1 < S) {
                int nb = (s + 1) & 1;
                mbar_expect(mbarf + nb * 8, FBYTES);
                bulk_g2s(f_dst + (unsigned)nb * FBYTES,
                         fsrc_grp + (size_t)(s + 1) * NGRP * IN * BPG,
                         FBYTES, mbarf + nb * 8);
            }
        }

        unsigned long long acc[16];
        #pragma unroll
        for (int i = 0; i < 16; i++) acc[i] = 0ull;

        // ---- input projection (feats prefetched last step -> no exposure) ----
        mbar_wait(mbarf + fb * 8, fpar);
        {
            const float* f_sm = sm + OFF_F + fb * (IN * BPG);
            #pragma unroll 2
            for (int k = foff; k < foff + fcnt; k++) {
                float4 hv = *(const float4*)(f_sm + k * BPG + bg * 4);
                ulonglong2 wa = *(const ulonglong2*)(Wi_t + k * 64 + rg * 8);
                ulonglong2 wb = *(const ulonglong2*)(Wi_t + k * 64 + rg * 8 + 4);
                STEP_K(hv, wa, wb);
            }
        }
        // ---- h-GEMM half 0 ----
        mbar_wait(mbar0 + (2 * kp) * 8, par);
        {
            const int k0 = kp * 64;
            #pragma unroll 8
            for (int k = k0; k < k0 + 32; k++) {
                float4 hv = *(const float4*)(h_sm + k * BPG + bg * 4);
                ulonglong2 wa = *(const ulonglong2*)(Wh_t + k * 64 + rg * 8);
                ulonglong2 wb = *(const ulonglong2*)(Wh_t + k * 64 + rg * 8 + 4);
                STEP_K(hv, wa, wb);
            }
        }
        // ---- half 1 ----
        mbar_wait(mbar0 + (2 * kp + 1) * 8, par);
        {
            const int k0 = kp * 64 + 32;
            #pragma unroll 8
            for (int k = k0; k < k0 + 32; k++) {
                float4 hv = *(const float4*)(h_sm + k * BPG + bg * 4);
                ulonglong2 wa = *(const ulonglong2*)(Wh_t + k * 64 + rg * 8);
                ulonglong2 wb = *(const ulonglong2*)(Wh_t + k * 64 + rg * 8 + 4);
                STEP_K(hv, wa, wb);
            }
        }

        // ---- partials: red[kp][16 b][66 r-pad], u64 row-pair stores ----
        {
            float* rp0 = red + (kp * BPG + bg * 4) * 66 + rg * 8;
            #pragma unroll
            for (int rp = 0; rp < 4; rp++) {
                #pragma unroll
                for (int j = 0; j < 4; j++) {
                    *(unsigned long long*)(rp0 + j * 66 + rp * 2) = acc[rp * 4 + j];
                }
            }
        }
        __syncthreads();

        // ---- reduce + gates ----
        {
            float g4[4];
            #pragma unroll
            for (int gt = 0; gt < 4; gt++) {
                int r = gt * UPC + ul;
                float v = bias[r];
                #pragma unroll
                for (int p = 0; p < 8; p++)
                    v += red[(p * BPG + gb) * 66 + r];
                g4[gt] = v;
            }
            float i_ = sigf(g4[0]);
            float f_ = sigf(g4[1]);
            float gg = tanhfast(g4[2]);
            float o_ = sigf(g4[3]);
            creg = f_ * creg + i_ * gg;
            float hn = o_ * tanhfast(creg);
            g_hbuf2[(size_t)(nxt * NGRP + grp) * H * BPG + u_glob * BPG + gb] = hn;
            g_lstm[((size_t)s * H + u_glob) * B + grp * BPG + gb] = hn;
        }

        // ---- group barrier: release-arrive + acquire-poll ----
        if (s != S - 1) {
            __syncthreads();
            if (t == 0) {
                asm volatile("red.add.release.gpu.u32 [%0], %1;"
                             :: "l"(my_ctr), "r"(1u) : "memory");
                unsigned target = (unsigned)(s + 1) * GCTA;
                unsigned v;
                do {
                    asm volatile("ld.acquire.gpu.u32 %0, [%1];"
                                 : "=r"(v) : "l"(my_ctr) : "memory");
                } while (v < target);
            }
            __syncthreads();
        }
    }
}

// ============================================================ attention
__global__ void __launch_bounds__(256)
scores_kernel(const float* __restrict__ attn_w) {
    __shared__ float aw[H];
    __shared__ float part[4 * 64];
    int t = threadIdx.x, s = blockIdx.x;
    int st = t >> 6, b = t & 63;
    for (int i = t; i < H; i += 256) aw[i] = attn_w[i];
    __syncthreads();
    const float* Ls = g_lstm + (size_t)s * H * B;
    float acc = 0.0f;
    #pragma unroll 8
    for (int h = st * 128; h < st * 128 + 128; h++)
        acc = fmaf(aw[h], Ls[h * B + b], acc);
    part[st * 64 + b] = acc;
    __syncthreads();
    if (st == 0)
        g_sc[s * B + b] = part[b] + part[64 + b] + part[128 + b] + part[192 + b];
}

__global__ void __launch_bounds__(256)
softmax_kernel(float* __restrict__ out) {
    __shared__ float s_red[8];
    int b = blockIdx.x, t = threadIdx.x;
    int lane = t & 31, warp = t >> 5;
    float v[2];
    v[0] = g_sc[t * B + b];
    v[1] = g_sc[(t + 256) * B + b];
    float m = fmaxf(v[0], v[1]);
    #pragma unroll
    for (int o = 16; o; o >>= 1) m = fmaxf(m, __shfl_xor_sync(~0u, m, o));
    if (lane == 0) s_red[warp] = m;
    __syncthreads();
    m = s_red[0];
    #pragma unroll
    for (int i = 1; i < 8; i++) m = fmaxf(m, s_red[i]);
    __syncthreads();
    float e0 = expf(v[0] - m), e1 = expf(v[1] - m);
    float sum = e0 + e1;
    #pragma unroll
    for (int o = 16; o; o >>= 1) sum += __shfl_xor_sync(~0u, sum, o);
    if (lane == 0) s_red[warp] = sum;
    __syncthreads();
    float tot = 0.0f;
    #pragma unroll
    for (int i = 0; i < 8; i++) tot += s_red[i];
    float inv = 1.0f / tot;
    float w0 = e0 * inv, w1 = e1 * inv;
    g_sc[t * B + b] = w0;
    g_sc[(t + 256) * B + b] = w1;
    out[NC * B + b * S + t] = w0;
    out[NC * B + b * S + t + 256] = w1;
}

__global__ void __launch_bounds__(256)
ctx_kernel() {
    __shared__ float part[4 * 64];
    int t = threadIdx.x, h = blockIdx.x;
    int st = t >> 6, b = t & 63;
    float acc = 0.0f;
    const float* Lb = g_lstm + (size_t)h * B + b;
    #pragma unroll 8
    for (int s = st * 128; s < st * 128 + 128; s++)
        acc = fmaf(g_sc[s * B + b], Lb[(size_t)s * H * B], acc);
    part[st * 64 + b] = acc;
    __syncthreads();
    if (st == 0)
        g_ctx[h * B + b] = part[b] + part[64 + b] + part[128 + b] + part[192 + b];
}

__global__ void __launch_bounds__(64)
fc_kernel(const float* __restrict__ fc_w, const float* __restrict__ fc_b,
          float* __restrict__ out) {
    __shared__ float wrow[H];
    int c = blockIdx.x, b = threadIdx.x;
    for (int i = b; i < H; i += 64) wrow[i] = fc_w[(size_t)c * H + i];
    __syncthreads();
    float acc = fc_b[c];
    #pragma unroll 8
    for (int h = 0; h < H; h++)
        acc = fmaf(wrow[h], g_ctx[h * B + b], acc);
    out[b * NC + c] = acc;
}

// ============================================================ launch
extern "C" void kernel_launch(void* const* d_in, const int* in_sizes, int n_in,
                              void* d_out, int out_size) {
    const float* x      = (const float*)d_in[0];
    const float* W_ih   = (const float*)d_in[1];
    const float* W_hh   = (const float*)d_in[2];
    const float* b_ih   = (const float*)d_in[3];
    const float* b_hh   = (const float*)d_in[4];
    const float* attn_w = (const float*)d_in[5];
    const float* fc_w   = (const float*)d_in[6];
    const float* fc_b   = (const float*)d_in[7];
    float* out = (float*)d_out;

    cudaFuncSetAttribute(lstm_kernel,
                         cudaFuncAttributeMaxDynamicSharedMemorySize, SMEM_BYTES);

    reset_kernel<<<(2 * NGRP * H * BPG + NTH - 1) / NTH, NTH>>>();
    prep_kernel<<<S, B>>>(x);
    lstm_kernel<<<NCTA, NTH, SMEM_BYTES>>>(W_ih, W_hh, b_ih, b_hh);
    scores_kernel<<<S, 256>>>(attn_w);
    softmax_kernel<<<B, 256>>>(out);
    ctx_kernel<<<H, 256>>>();
    fc_kernel<<<NC, 64>>>(fc_w, fc_b, out);
}

// round 11
// speedup vs baseline: 1.3691x; 1.2976x over previous
#include <cuda_runtime.h>
#include <cuda_bf16.h>
#include <math.h>

#define B 64
#define S 512
#define H 512
#define IN 84
#define NC 100
#define XW 266

#define NGRP 4
#define GCTA 32
#define BPG 16
#define UPC 16
#define NCTA 128
#define NTH 256

// padded strides (halves): consecutive rows 16B apart mod 128 -> conflict-free ldmatrix
#define WST 648
#define XHST 520
#define XFST 136

// ---- static device scratch ----
__device__ unsigned short g_hx[2 * NGRP * 2 * 16 * XHST];        // [par][grp][hi/lo][16b][520]
__device__ unsigned short g_fx[(size_t)S * NGRP * 2 * 16 * XFST];// [s][grp][hi/lo][16b][136]
__device__ float g_lstm[(size_t)S * H * B];                      // [S][H][B]
__device__ float g_sc[S * B];
__device__ float g_ctx[H * B];
__device__ unsigned g_ctrs[64];

// ---- SMEM layout (bytes) ----
#define OFF_WHI   0                     // 64 x 648 bf16 = 82944
#define OFF_WLO   82944
#define OFF_XH_HI 165888                // 16 x 520 bf16 = 16640
#define OFF_XH_LO 182528
#define OFF_XF    199168                // 2 bufs x (hi+lo) x 16 x 136 bf16 = 17408
#define OFF_GSH   216576                // 64 x 17 f32
#define OFF_HOUT  220928                // 16 x 17 f32
#define OFF_MB    222016                // 3 mbars
#define SMEM_BYTES 222048
#define XFBUF 8704                      // bytes per feats buffer (hi+lo)

// ---- helpers ----
__device__ __forceinline__ unsigned smem_u32(const void* p) {
    return (unsigned)__cvta_generic_to_shared(p);
}
__device__ __forceinline__ void mbar_init(unsigned a, unsigned cnt) {
    asm volatile("mbarrier.init.shared.b64 [%0], %1;" :: "r"(a), "r"(cnt) : "memory");
}
__device__ __forceinline__ void mbar_expect(unsigned a, unsigned bytes) {
    asm volatile("mbarrier.arrive.expect_tx.shared.b64 _, [%0], %1;"
                 :: "r"(a), "r"(bytes) : "memory");
}
__device__ __forceinline__ void bulk_g2s(unsigned dst, const void* src,
                                         unsigned bytes, unsigned mbar) {
    asm volatile(
        "cp.async.bulk.shared::cluster.global.mbarrier::complete_tx::bytes "
        "[%0], [%1], %2, [%3];"
        :: "r"(dst), "l"(src), "r"(bytes), "r"(mbar) : "memory");
}
__device__ __forceinline__ void mbar_wait(unsigned a, unsigned parity) {
    asm volatile(
        "{\n\t.reg .pred P;\n\t"
        "W%=:\n\t"
        "mbarrier.try_wait.parity.shared.b64 P, [%0], %1, 0x989680;\n\t"
        "@P bra D%=;\n\t"
        "bra W%=;\n\t"
        "D%=:\n\t}"
        :: "r"(a), "r"(parity) : "memory");
}

#define LDSM4(r, addr) \
    asm volatile("ldmatrix.sync.aligned.m8n8.x4.shared.b16 {%0,%1,%2,%3}, [%4];" \
        : "=r"((r)[0]), "=r"((r)[1]), "=r"((r)[2]), "=r"((r)[3]) : "r"(addr))
#define MMA16816(c, a, b0v, b1v) \
    asm volatile("mma.sync.aligned.m16n8k16.row.col.f32.bf16.bf16.f32 " \
        "{%0,%1,%2,%3}, {%4,%5,%6,%7}, {%8,%9}, {%0,%1,%2,%3};" \
        : "+f"((c)[0]), "+f"((c)[1]), "+f"((c)[2]), "+f"((c)[3]) \
        : "r"((a)[0]), "r"((a)[1]), "r"((a)[2]), "r"((a)[3]), "r"(b0v), "r"(b1v))

// one k-step: A hi/lo fragments + B hi/lo fragments (B stored [n][k] -> non-trans
// ldmatrix gives the m16n8k16 col-major B fragment directly), 3 split passes x 2 n-halves
// B reg map (lane addressing below): r0=(n0-7,k0-7) r1=(n0-7,k8-15) r2=(n8-15,k0-7) r3=(n8-15,k8-15)
#define KSTEP(aHI, aLO, bHI, bLO) do {                    \
    unsigned ah[4], al[4], bh[4], bl[4];                  \
    LDSM4(ah, aHI); LDSM4(al, aLO);                       \
    LDSM4(bh, bHI); LDSM4(bl, bLO);                       \
    MMA16816(cn0, ah, bh[0], bh[1]);                      \
    MMA16816(cn1, ah, bh[2], bh[3]);                      \
    MMA16816(cn0, al, bh[0], bh[1]);                      \
    MMA16816(cn1, al, bh[2], bh[3]);                      \
    MMA16816(cn0, ah, bl[0], bl[1]);                      \
    MMA16816(cn1, ah, bl[2], bl[3]);                      \
} while (0)

__device__ __forceinline__ float sigf(float x) {
    return __fdividef(1.0f, 1.0f + __expf(-x));
}
__device__ __forceinline__ float tanhfast(float x) {
    return __fdividef(2.0f, 1.0f + __expf(-2.0f * x)) - 1.0f;
}
__device__ __forceinline__ unsigned short bf16r(float v) {
    __nv_bfloat16 h = __float2bfloat16(v);
    unsigned short r; memcpy(&r, &h, 2); return r;
}

// ============================================================ reset
__global__ void reset_kernel() {
    int t = blockIdx.x * blockDim.x + threadIdx.x;
    if (t < 64) g_ctrs[t] = 0u;
    if (t < (int)(sizeof(g_hx) / 4)) ((unsigned*)g_hx)[t] = 0u;
}

// ============================================================ preprocessing
__global__ void prep_kernel(const float* __restrict__ x) {
    int s = blockIdx.x;
    int b = threadIdx.x;                 // 64 threads
    int grp = b >> 4, bl = b & 15;
    unsigned short* fh = g_fx + (((size_t)s * NGRP + grp) * 2 + 0) * 16 * XFST + bl * XFST;
    unsigned short* fl = g_fx + (((size_t)s * NGRP + grp) * 2 + 1) * 16 * XFST + bl * XFST;
    #pragma unroll 4
    for (int c = 0; c < XFST; c++) { fh[c] = 0; fl[c] = 0; }

    const float* xp = x + ((size_t)b * S + s) * XW;
    float cx = xp[0], cy = xp[1];
    #pragma unroll
    for (int hnd = 0; hnd < 2; hnd++) {
        int pbase = (hnd == 0) ? 91 : 112;
        float mnx = 1e30f, mxx = -1e30f, mny = 1e30f, mxy = -1e30f;
        #pragma unroll
        for (int p = 0; p < 21; p++) {
            float px = xp[(pbase + p) * 2];
            float py = xp[(pbase + p) * 2 + 1];
            mnx = fminf(mnx, px); mxx = fmaxf(mxx, px);
            mny = fminf(mny, py); mxy = fmaxf(mxy, py);
        }
        float whx = mxx - mnx, why = mxy - mny;
        bool ok = (whx != 0.0f) && (why != 0.0f);
        float sx = ok ? whx : 1.0f;
        float sy = ok ? why : 1.0f;
        #pragma unroll
        for (int p = 0; p < 21; p++) {
            float px = (xp[(pbase + p) * 2] - cx) / sx;
            float py = (xp[(pbase + p) * 2 + 1] - cy) / sy;
            int i0 = hnd * 42 + p * 2;
            unsigned short h0 = bf16r(px), h1 = bf16r(py);
            __nv_bfloat16 b0, b1; memcpy(&b0, &h0, 2); memcpy(&b1, &h1, 2);
            fh[i0]     = h0; fl[i0]     = bf16r(px - __bfloat162float(b0));
            fh[i0 + 1] = h1; fl[i0 + 1] = bf16r(py - __bfloat162float(b1));
        }
    }
    fh[84] = bf16r(1.0f);   // bias row
    fl[84] = 0;
}

// ============================================================ recurrence (HMMA)
__global__ void __launch_bounds__(NTH, 1)
lstm_kernel(const float* __restrict__ W_ih, const float* __restrict__ W_hh,
            const float* __restrict__ b_ih, const float* __restrict__ b_hh) {
    extern __shared__ char smc[];
    const int t = threadIdx.x;
    const int blk = blockIdx.x;
    const int grp = blk >> 5;
    const int cg = blk & 31;
    const int lane = t & 31;
    const int wid = t >> 5;
    const unsigned sbase = smem_u32(smc);

    // ---- one-time W staging: bf16 hi/lo [64 rows][648 cols], row = gate*16+unit ----
    for (int idx = t; idx < 64 * 640; idx += NTH) {
        int r = idx & 63, k = idx >> 6;
        int grow = (r >> 4) * H + cg * UPC + (r & 15);
        float w;
        if (k < 512)        w = W_hh[(size_t)grow * H + k];
        else if (k < 596)   w = W_ih[(size_t)grow * IN + (k - 512)];
        else if (k == 596)  w = b_ih[grow] + b_hh[grow];
        else                w = 0.0f;
        __nv_bfloat16 hi = __float2bfloat16(w);
        __nv_bfloat16 lo = __float2bfloat16(w - __bfloat162float(hi));
        ((__nv_bfloat16*)(smc + OFF_WHI))[r * WST + k] = hi;
        ((__nv_bfloat16*)(smc + OFF_WLO))[r * WST + k] = lo;
    }
    if (t == 0) {
        mbar_init(sbase + OFF_MB + 0, 1);    // h
        mbar_init(sbase + OFF_MB + 8, 1);    // feats buf0
        mbar_init(sbase + OFF_MB + 16, 1);   // feats buf1
    }
    __syncthreads();

    const unsigned mbh = sbase + OFF_MB;
    const unsigned mbf = sbase + OFF_MB + 8;

    // ldmatrix per-lane addresses
    // A (row-major 16x16): lanes 0-7 rows 0-7 @k, 8-15 rows 8-15 @k, 16-23 rows 0-7 @k+8, ...
    const unsigned aA = (unsigned)(((wid & 3) * 16 + (lane & 15)) * WST + (lane >> 4) * 8) * 2;
    const unsigned aAhi = sbase + OFF_WHI + aA;
    const unsigned aAlo = sbase + OFF_WLO + aA;
    // B non-trans from [n][k] storage:
    //  lanes 0-7:  n 0-7,  k+0   -> reg0
    //  lanes 8-15: n 0-7,  k+8   -> reg1
    //  lanes 16-23:n 8-15, k+0   -> reg2
    //  lanes 24-31:n 8-15, k+8   -> reg3
    const unsigned nrow = (lane & 7) + ((lane >> 4) & 1) * 8;
    const unsigned kofs = ((lane >> 3) & 1) * 8;
    const unsigned aBh = (unsigned)(nrow * XHST + kofs) * 2;
    const unsigned aBhhi = sbase + OFF_XH_HI + aBh;
    const unsigned aBhlo = sbase + OFF_XH_LO + aBh;
    const unsigned aBf = (unsigned)(nrow * XFST + kofs) * 2;

    // gate mapping
    const int ul = t & 15, gb = t >> 4;
    const int u_glob = cg * UPC + ul;
    float creg = 0.0f;

    float* gsh  = (float*)(smc + OFF_GSH);
    float* hout = (float*)(smc + OFF_HOUT);
    unsigned* my_ctr = &g_ctrs[grp * 16];
    const unsigned short* hsrc_base = g_hx + (size_t)grp * 2 * 16 * XHST;
    const unsigned short* fsrc_base = g_fx + (size_t)grp * 2 * 16 * XFST;

    // prefetch feats s=0 into buf 0
    if (t == 0) {
        asm volatile("fence.proxy.async;" ::: "memory");
        mbar_expect(mbf, XFBUF);
        bulk_g2s(sbase + OFF_XF, fsrc_base, XFBUF, mbf);
    }

    for (int s = 0; s < S; s++) {
        const int cur = s & 1, nxt = cur ^ 1;
        const unsigned par = (unsigned)(s & 1);
        const int fb = s & 1;
        const unsigned fpar = (unsigned)((s >> 1) & 1);

        // ---- t0 issues h copy (hi+lo contiguous) + feats prefetch for s+1 ----
        if (t == 0) {
            asm volatile("fence.proxy.async;" ::: "memory");
            mbar_expect(mbh, 2 * 16 * XHST * 2);
            bulk_g2s(sbase + OFF_XH_HI,
                     hsrc_base + (size_t)cur * NGRP * 2 * 16 * XHST,
                     2 * 16 * XHST * 2, mbh);
            if (s + 1 < S) {
                int nb = (s + 1) & 1;
                mbar_expect(mbf + nb * 8, XFBUF);
                bulk_g2s(sbase + OFF_XF + (unsigned)nb * XFBUF,
                         fsrc_base + (size_t)(s + 1) * NGRP * 2 * 16 * XFST,
                         XFBUF, mbf + nb * 8);
            }
        }

        if (wid < 4) {
            float cn0[4] = {0, 0, 0, 0};
            float cn1[4] = {0, 0, 0, 0};

            // ---- feats k-steps first (prefetched; W cols 512..639) ----
            mbar_wait(mbf + fb * 8, fpar);
            {
                const unsigned fhi = sbase + OFF_XF + (unsigned)fb * XFBUF + aBf;
                const unsigned flo = fhi + 16 * XFST * 2;
                #pragma unroll
                for (int j = 0; j < 8; j++) {
                    KSTEP(aAhi + 1024 + j * 32, aAlo + 1024 + j * 32,
                          fhi + j * 32, flo + j * 32);
                }
            }
            // ---- h k-steps (W cols 0..511) ----
            mbar_wait(mbh, par);
            #pragma unroll 4
            for (int j = 0; j < 32; j++) {
                KSTEP(aAhi + j * 32, aAlo + j * 32,
                      aBhhi + j * 32, aBhlo + j * 32);
            }

            // ---- D writeback to gsh[64][17] ----
            {
                int r0 = (wid & 3) * 16 + (lane >> 2);
                int c0 = (lane & 3) * 2;
                gsh[r0 * 17 + c0]           = cn0[0];
                gsh[r0 * 17 + c0 + 1]       = cn0[1];
                gsh[(r0 + 8) * 17 + c0]     = cn0[2];
                gsh[(r0 + 8) * 17 + c0 + 1] = cn0[3];
                gsh[r0 * 17 + 8 + c0]           = cn1[0];
                gsh[r0 * 17 + 8 + c0 + 1]       = cn1[1];
                gsh[(r0 + 8) * 17 + 8 + c0]     = cn1[2];
                gsh[(r0 + 8) * 17 + 8 + c0 + 1] = cn1[3];
            }
        }
        __syncthreads();

        // ---- gates: thread = (unit ul, batch gb) ----
        {
            float gi = gsh[(0 * 16 + ul) * 17 + gb];
            float gf = gsh[(1 * 16 + ul) * 17 + gb];
            float gg = gsh[(2 * 16 + ul) * 17 + gb];
            float go = gsh[(3 * 16 + ul) * 17 + gb];
            float i_ = sigf(gi), f_ = sigf(gf);
            float g_ = tanhfast(gg), o_ = sigf(go);
            creg = f_ * creg + i_ * g_;
            float hn = o_ * tanhfast(creg);
            __nv_bfloat16 hi = __float2bfloat16(hn);
            unsigned short hr; memcpy(&hr, &hi, 2);
            unsigned short lr = bf16r(hn - __bfloat162float(hi));
            size_t hbase = (size_t)(nxt * NGRP + grp) * 2 * 16 * XHST;
            g_hx[hbase + gb * XHST + u_glob] = hr;                       // hi plane
            g_hx[hbase + 16 * XHST + gb * XHST + u_glob] = lr;           // lo plane
            hout[ul * 17 + gb] = hn;
        }
        __syncthreads();
        {
            int u2 = t >> 4, b2 = t & 15;
            g_lstm[((size_t)s * H + cg * UPC + u2) * B + grp * BPG + b2] =
                hout[u2 * 17 + b2];
        }

        // ---- group barrier ----
        if (s != S - 1) {
            if (t == 0) {
                asm volatile("red.add.release.gpu.u32 [%0], %1;"
                             :: "l"(my_ctr), "r"(1u) : "memory");
                unsigned target = (unsigned)(s + 1) * GCTA;
                unsigned v;
                do {
                    asm volatile("ld.acquire.gpu.u32 %0, [%1];"
                                 : "=r"(v) : "l"(my_ctr) : "memory");
                } while (v < target);
            }
            __syncthreads();
        }
    }
}

// ============================================================ attention
__global__ void __launch_bounds__(256)
scores_kernel(const float* __restrict__ attn_w) {
    __shared__ float aw[H];
    __shared__ float part[4 * 64];
    int t = threadIdx.x, s = blockIdx.x;
    int st = t >> 6, b = t & 63;
    for (int i = t; i < H; i += 256) aw[i] = attn_w[i];
    __syncthreads();
    const float* Ls = g_lstm + (size_t)s * H * B;
    float acc = 0.0f;
    #pragma unroll 8
    for (int h = st * 128; h < st * 128 + 128; h++)
        acc = fmaf(aw[h], Ls[h * B + b], acc);
    part[st * 64 + b] = acc;
    __syncthreads();
    if (st == 0)
        g_sc[s * B + b] = part[b] + part[64 + b] + part[128 + b] + part[192 + b];
}

__global__ void __launch_bounds__(256)
softmax_kernel(float* __restrict__ out) {
    __shared__ float s_red[8];
    int b = blockIdx.x, t = threadIdx.x;
    int lane = t & 31, warp = t >> 5;
    float v[2];
    v[0] = g_sc[t * B + b];
    v[1] = g_sc[(t + 256) * B + b];
    float m = fmaxf(v[0], v[1]);
    #pragma unroll
    for (int o = 16; o; o >>= 1) m = fmaxf(m, __shfl_xor_sync(~0u, m, o));
    if (lane == 0) s_red[warp] = m;
    __syncthreads();
    m = s_red[0];
    #pragma unroll
    for (int i = 1; i < 8; i++) m = fmaxf(m, s_red[i]);
    __syncthreads();
    float e0 = expf(v[0] - m), e1 = expf(v[1] - m);
    float sum = e0 + e1;
    #pragma unroll
    for (int o = 16; o; o >>= 1) sum += __shfl_xor_sync(~0u, sum, o);
    if (lane == 0) s_red[warp] = sum;
    __syncthreads();
    float tot = 0.0f;
    #pragma unroll
    for (int i = 0; i < 8; i++) tot += s_red[i];
    float inv = 1.0f / tot;
    float w0 = e0 * inv, w1 = e1 * inv;
    g_sc[t * B + b] = w0;
    g_sc[(t + 256) * B + b] = w1;
    out[NC * B + b * S + t] = w0;
    out[NC * B + b * S + t + 256] = w1;
}

__global__ void __launch_bounds__(256)
ctx_kernel() {
    __shared__ float part[4 * 64];
    int t = threadIdx.x, h = blockIdx.x;
    int st = t >> 6, b = t & 63;
    float acc = 0.0f;
    const float* Lb = g_lstm + (size_t)h * B + b;
    #pragma unroll 8
    for (int s = st * 128; s < st * 128 + 128; s++)
        acc = fmaf(g_sc[s * B + b], Lb[(size_t)s * H * B], acc);
    part[st * 64 + b] = acc;
    __syncthreads();
    if (st == 0)
        g_ctx[h * B + b] = part[b] + part[64 + b] + part[128 + b] + part[192 + b];
}

__global__ void __launch_bounds__(64)
fc_kernel(const float* __restrict__ fc_w, const float* __restrict__ fc_b,
          float* __restrict__ out) {
    __shared__ float wrow[H];
    int c = blockIdx.x, b = threadIdx.x;
    for (int i = b; i < H; i += 64) wrow[i] = fc_w[(size_t)c * H + i];
    __syncthreads();
    float acc = fc_b[c];
    #pragma unroll 8
    for (int h = 0; h < H; h++)
        acc = fmaf(wrow[h], g_ctx[h * B + b], acc);
    out[b * NC + c] = acc;
}

// ============================================================ launch
extern "C" void kernel_launch(void* const* d_in, const int* in_sizes, int n_in,
                              void* d_out, int out_size) {
    const float* x      = (const float*)d_in[0];
    const float* W_ih   = (const float*)d_in[1];
    const float* W_hh   = (const float*)d_in[2];
    const float* b_ih   = (const float*)d_in[3];
    const float* b_hh   = (const float*)d_in[4];
    const float* attn_w = (const float*)d_in[5];
    const float* fc_w   = (const float*)d_in[6];
    const float* fc_b   = (const float*)d_in[7];
    float* out = (float*)d_out;

    cudaFuncSetAttribute(lstm_kernel,
                         cudaFuncAttributeMaxDynamicSharedMemorySize, SMEM_BYTES);

    reset_kernel<<<260, 256>>>();
    prep_kernel<<<S, 64>>>(x);
    lstm_kernel<<<NCTA, NTH, SMEM_BYTES>>>(W_ih, W_hh, b_ih, b_hh);
    scores_kernel<<<S, 256>>>(attn_w);
    softmax_kernel<<<B, 256>>>(out);
    ctx_kernel<<<H, 256>>>();
    fc_kernel<<<NC, 64>>>(fc_w, fc_b, out);
}

// round 12
// speedup vs baseline: 1.6150x; 1.1796x over previous
#include <cuda_runtime.h>
#include <cuda_fp16.h>
#include <math.h>

#define B 64
#define S 512
#define H 512
#define IN 84
#define NC 100
#define XW 266

#define NGRP 4
#define GCTA 32
#define BPG 16
#define UPC 16
#define NCTA 128
#define NTH 256

// padded strides (halves): row stride ≡ odd*16 B mod 128 -> conflict-free ldmatrix
#define WST 648
#define XHST 520
#define XFST 136

#define INV256 0.00390625f

// ---- static device scratch ----
__device__ unsigned short g_hx[2 * NGRP * 16 * XHST];            // [par][grp][16b][520] fp16
__device__ unsigned short g_fx[(size_t)S * NGRP * 16 * XFST];    // [s][grp][16b][136] fp16
__device__ float g_lstm[(size_t)S * H * B];                      // [S][H][B]
__device__ float g_sc[S * B];
__device__ float g_ctx[H * B];
__device__ unsigned g_ctrs[64];

// ---- SMEM layout (bytes) ----
#define OFF_WHI   0                     // 64 x 648 fp16 = 82944
#define OFF_WLO   82944                 // Wlo * 256, fp16
#define OFF_XH    165888                // 16 x 520 fp16 = 16640
#define OFF_XF    182528                // 2 bufs x 16 x 136 fp16 = 8704
#define OFF_GSH   191232                // 64 x 17 f32
#define OFF_HOUT  195584                // 16 x 17 f32
#define OFF_MB    196672                // 3 mbars
#define SMEM_BYTES 196704
#define XFBUF 4352                      // bytes per feats buffer
#define XHBYTES 16640                   // h plane bytes

// ---- helpers ----
__device__ __forceinline__ unsigned smem_u32(const void* p) {
    return (unsigned)__cvta_generic_to_shared(p);
}
__device__ __forceinline__ void mbar_init(unsigned a, unsigned cnt) {
    asm volatile("mbarrier.init.shared.b64 [%0], %1;" :: "r"(a), "r"(cnt) : "memory");
}
__device__ __forceinline__ void mbar_expect(unsigned a, unsigned bytes) {
    asm volatile("mbarrier.arrive.expect_tx.shared.b64 _, [%0], %1;"
                 :: "r"(a), "r"(bytes) : "memory");
}
__device__ __forceinline__ void bulk_g2s(unsigned dst, const void* src,
                                         unsigned bytes, unsigned mbar) {
    asm volatile(
        "cp.async.bulk.shared::cluster.global.mbarrier::complete_tx::bytes "
        "[%0], [%1], %2, [%3];"
        :: "r"(dst), "l"(src), "r"(bytes), "r"(mbar) : "memory");
}
__device__ __forceinline__ void mbar_wait(unsigned a, unsigned parity) {
    asm volatile(
        "{\n\t.reg .pred P;\n\t"
        "W%=:\n\t"
        "mbarrier.try_wait.parity.shared.b64 P, [%0], %1, 0x989680;\n\t"
        "@P bra D%=;\n\t"
        "bra W%=;\n\t"
        "D%=:\n\t}"
        :: "r"(a), "r"(parity) : "memory");
}

#define LDSM4(r, addr) \
    asm volatile("ldmatrix.sync.aligned.m8n8.x4.shared.b16 {%0,%1,%2,%3}, [%4];" \
        : "=r"((r)[0]), "=r"((r)[1]), "=r"((r)[2]), "=r"((r)[3]) : "r"(addr))
#define MMAH16816(c, a, b0v, b1v) \
    asm volatile("mma.sync.aligned.m16n8k16.row.col.f32.f16.f16.f32 " \
        "{%0,%1,%2,%3}, {%4,%5,%6,%7}, {%8,%9}, {%0,%1,%2,%3};" \
        : "+f"((c)[0]), "+f"((c)[1]), "+f"((c)[2]), "+f"((c)[3]) \
        : "r"((a)[0]), "r"((a)[1]), "r"((a)[2]), "r"((a)[3]), "r"(b0v), "r"(b1v))

// one k-step: A hi + A lo(scaled) fragments, single-plane B; 2-pass into (cn, dn)
// B reg map: r0=(n0-7,k0-7) r1=(n0-7,k8-15) r2=(n8-15,k0-7) r3=(n8-15,k8-15)
#define KSTEP2(aHI, aLO, bADDR) do {                      \
    unsigned ah[4], al[4], bh[4];                         \
    LDSM4(ah, aHI); LDSM4(al, aLO); LDSM4(bh, bADDR);     \
    MMAH16816(cn0, ah, bh[0], bh[1]);                     \
    MMAH16816(cn1, ah, bh[2], bh[3]);                     \
    MMAH16816(dn0, al, bh[0], bh[1]);                     \
    MMAH16816(dn1, al, bh[2], bh[3]);                     \
} while (0)

__device__ __forceinline__ float sigf(float x) {
    return __fdividef(1.0f, 1.0f + __expf(-x));
}
__device__ __forceinline__ float tanhfast(float x) {
    return __fdividef(2.0f, 1.0f + __expf(-2.0f * x)) - 1.0f;
}
__device__ __forceinline__ unsigned short f16r(float v) {
    __half h = __float2half_rn(v);
    unsigned short r; memcpy(&r, &h, 2); return r;
}

// ============================================================ reset
__global__ void reset_kernel() {
    int t = blockIdx.x * blockDim.x + threadIdx.x;
    if (t < 64) g_ctrs[t] = 0u;
    if (t < (int)(sizeof(g_hx) / 4)) ((unsigned*)g_hx)[t] = 0u;
}

// ============================================================ preprocessing
__global__ void prep_kernel(const float* __restrict__ x) {
    int s = blockIdx.x;
    int b = threadIdx.x;                 // 64 threads
    int grp = b >> 4, bl = b & 15;
    unsigned short* fh = g_fx + ((size_t)s * NGRP + grp) * 16 * XFST + bl * XFST;
    #pragma unroll 4
    for (int c = 0; c < XFST; c++) fh[c] = 0;

    const float* xp = x + ((size_t)b * S + s) * XW;
    float cx = xp[0], cy = xp[1];
    #pragma unroll
    for (int hnd = 0; hnd < 2; hnd++) {
        int pbase = (hnd == 0) ? 91 : 112;
        float mnx = 1e30f, mxx = -1e30f, mny = 1e30f, mxy = -1e30f;
        #pragma unroll
        for (int p = 0; p < 21; p++) {
            float px = xp[(pbase + p) * 2];
            float py = xp[(pbase + p) * 2 + 1];
            mnx = fminf(mnx, px); mxx = fmaxf(mxx, px);
            mny = fminf(mny, py); mxy = fmaxf(mxy, py);
        }
        float whx = mxx - mnx, why = mxy - mny;
        bool ok = (whx != 0.0f) && (why != 0.0f);
        float sx = ok ? whx : 1.0f;
        float sy = ok ? why : 1.0f;
        #pragma unroll
        for (int p = 0; p < 21; p++) {
            float px = (xp[(pbase + p) * 2] - cx) / sx;
            float py = (xp[(pbase + p) * 2 + 1] - cy) / sy;
            int i0 = hnd * 42 + p * 2;
            fh[i0]     = f16r(px);
            fh[i0 + 1] = f16r(py);
        }
    }
    fh[84] = f16r(1.0f);   // bias row
}

// ============================================================ recurrence (fp16 HMMA 2-pass)
__global__ void __launch_bounds__(NTH, 1)
lstm_kernel(const float* __restrict__ W_ih, const float* __restrict__ W_hh,
            const float* __restrict__ b_ih, const float* __restrict__ b_hh) {
    extern __shared__ char smc[];
    const int t = threadIdx.x;
    const int blk = blockIdx.x;
    const int grp = blk >> 5;
    const int cg = blk & 31;
    const int lane = t & 31;
    const int wid = t >> 5;
    const unsigned sbase = smem_u32(smc);

    // ---- one-time W staging: fp16 hi + scaled lo, [64 rows][648 cols] (cols < 608 live) ----
    for (int idx = t; idx < 64 * 608; idx += NTH) {
        int r = idx & 63, k = idx >> 6;
        int grow = (r >> 4) * H + cg * UPC + (r & 15);
        float w;
        if (k < 512)        w = W_hh[(size_t)grow * H + k];
        else if (k < 596)   w = W_ih[(size_t)grow * IN + (k - 512)];
        else if (k == 596)  w = b_ih[grow] + b_hh[grow];
        else                w = 0.0f;
        __half hi = __float2half_rn(w);
        __half lo = __float2half_rn((w - __half2float(hi)) * 256.0f);
        ((__half*)(smc + OFF_WHI))[r * WST + k] = hi;
        ((__half*)(smc + OFF_WLO))[r * WST + k] = lo;
    }
    if (t == 0) {
        mbar_init(sbase + OFF_MB + 0, 1);    // h
        mbar_init(sbase + OFF_MB + 8, 1);    // feats buf0
        mbar_init(sbase + OFF_MB + 16, 1);   // feats buf1
    }
    __syncthreads();

    const unsigned mbh = sbase + OFF_MB;
    const unsigned mbf = sbase + OFF_MB + 8;

    // ldmatrix per-lane addresses
    // A (row-major 16x16): lanes 0-15 rows 0-15 @k, lanes 16-31 rows 0-15 @k+8
    const unsigned aA = (unsigned)(((wid & 3) * 16 + (lane & 15)) * WST + (lane >> 4) * 8) * 2;
    const unsigned aAhi = sbase + OFF_WHI + aA;
    const unsigned aAlo = sbase + OFF_WLO + aA;
    // B non-trans from [n][k] storage:
    //  lanes 0-7: n0-7,k+0 | 8-15: n0-7,k+8 | 16-23: n8-15,k+0 | 24-31: n8-15,k+8
    const unsigned nrow = (lane & 7) + ((lane >> 4) & 1) * 8;
    const unsigned kofs = ((lane >> 3) & 1) * 8;
    const unsigned aBh = sbase + OFF_XH + (unsigned)(nrow * XHST + kofs) * 2;
    const unsigned aBf = (unsigned)(nrow * XFST + kofs) * 2;

    // gate mapping
    const int ul = t & 15, gb = t >> 4;
    const int u_glob = cg * UPC + ul;
    float creg = 0.0f;

    float* gsh  = (float*)(smc + OFF_GSH);
    float* hout = (float*)(smc + OFF_HOUT);
    unsigned* my_ctr = &g_ctrs[grp * 16];
    const unsigned short* hsrc_base = g_hx + (size_t)grp * 16 * XHST;
    const unsigned short* fsrc_base = g_fx + (size_t)grp * 16 * XFST;

    // prefetch feats s=0 into buf 0
    if (t == 0) {
        asm volatile("fence.proxy.async;" ::: "memory");
        mbar_expect(mbf, XFBUF);
        bulk_g2s(sbase + OFF_XF, fsrc_base, XFBUF, mbf);
    }

    for (int s = 0; s < S; s++) {
        const int cur = s & 1, nxt = cur ^ 1;
        const unsigned par = (unsigned)(s & 1);
        const int fb = s & 1;
        const unsigned fpar = (unsigned)((s >> 1) & 1);

        // ---- t0 issues h copy + feats prefetch for s+1 ----
        if (t == 0) {
            asm volatile("fence.proxy.async;" ::: "memory");
            mbar_expect(mbh, XHBYTES);
            bulk_g2s(sbase + OFF_XH,
                     hsrc_base + (size_t)cur * NGRP * 16 * XHST,
                     XHBYTES, mbh);
            if (s + 1 < S) {
                int nb = (s + 1) & 1;
                mbar_expect(mbf + nb * 8, XFBUF);
                bulk_g2s(sbase + OFF_XF + (unsigned)nb * XFBUF,
                         fsrc_base + (size_t)(s + 1) * NGRP * 16 * XFST,
                         XFBUF, mbf + nb * 8);
            }
        }

        if (wid < 4) {
            float cn0[4] = {0, 0, 0, 0};
            float cn1[4] = {0, 0, 0, 0};
            float dn0[4] = {0, 0, 0, 0};
            float dn1[4] = {0, 0, 0, 0};

            // ---- feats k-steps first (prefetched; W cols 512..607, 6 ksteps) ----
            mbar_wait(mbf + fb * 8, fpar);
            {
                const unsigned fba = sbase + OFF_XF + (unsigned)fb * XFBUF + aBf;
                #pragma unroll
                for (int j = 0; j < 6; j++) {
                    KSTEP2(aAhi + 1024 + j * 32, aAlo + 1024 + j * 32,
                           fba + j * 32);
                }
            }
            // ---- h k-steps (W cols 0..511, 32 ksteps) ----
            mbar_wait(mbh, par);
            #pragma unroll 4
            for (int j = 0; j < 32; j++) {
                KSTEP2(aAhi + j * 32, aAlo + j * 32, aBh + j * 32);
            }

            // ---- combine passes + D writeback to gsh[64][17] ----
            {
                int r0 = (wid & 3) * 16 + (lane >> 2);
                int c0 = (lane & 3) * 2;
                gsh[r0 * 17 + c0]           = cn0[0] + dn0[0] * INV256;
                gsh[r0 * 17 + c0 + 1]       = cn0[1] + dn0[1] * INV256;
                gsh[(r0 + 8) * 17 + c0]     = cn0[2] + dn0[2] * INV256;
                gsh[(r0 + 8) * 17 + c0 + 1] = cn0[3] + dn0[3] * INV256;
                gsh[r0 * 17 + 8 + c0]           = cn1[0] + dn1[0] * INV256;
                gsh[r0 * 17 + 8 + c0 + 1]       = cn1[1] + dn1[1] * INV256;
                gsh[(r0 + 8) * 17 + 8 + c0]     = cn1[2] + dn1[2] * INV256;
                gsh[(r0 + 8) * 17 + 8 + c0 + 1] = cn1[3] + dn1[3] * INV256;
            }
        }
        __syncthreads();

        // ---- gates: thread = (unit ul, batch gb) ----
        {
            float gi = gsh[(0 * 16 + ul) * 17 + gb];
            float gf = gsh[(1 * 16 + ul) * 17 + gb];
            float gg = gsh[(2 * 16 + ul) * 17 + gb];
            float go = gsh[(3 * 16 + ul) * 17 + gb];
            float i_ = sigf(gi), f_ = sigf(gf);
            float g_ = tanhfast(gg), o_ = sigf(go);
            creg = f_ * creg + i_ * g_;
            float hn = o_ * tanhfast(creg);
            size_t hbase = (size_t)(nxt * NGRP + grp) * 16 * XHST;
            g_hx[hbase + gb * XHST + u_glob] = f16r(hn);
            hout[ul * 17 + gb] = hn;
        }
        __syncthreads();
        {
            int u2 = t >> 4, b2 = t & 15;
            g_lstm[((size_t)s * H + cg * UPC + u2) * B + grp * BPG + b2] =
                hout[u2 * 17 + b2];
        }

        // ---- group barrier ----
        if (s != S - 1) {
            if (t == 0) {
                asm volatile("red.add.release.gpu.u32 [%0], %1;"
                             :: "l"(my_ctr), "r"(1u) : "memory");
                unsigned target = (unsigned)(s + 1) * GCTA;
                unsigned v;
                do {
                    asm volatile("ld.acquire.gpu.u32 %0, [%1];"
                                 : "=r"(v) : "l"(my_ctr) : "memory");
                } while (v < target);
            }
            __syncthreads();
        }
    }
}

// ============================================================ attention
__global__ void __launch_bounds__(256)
scores_kernel(const float* __restrict__ attn_w) {
    __shared__ float aw[H];
    __shared__ float part[4 * 64];
    int t = threadIdx.x, s = blockIdx.x;
    int st = t >> 6, b = t & 63;
    for (int i = t; i < H; i += 256) aw[i] = attn_w[i];
    __syncthreads();
    const float* Ls = g_lstm + (size_t)s * H * B;
    float acc = 0.0f;
    #pragma unroll 8
    for (int h = st * 128; h < st * 128 + 128; h++)
        acc = fmaf(aw[h], Ls[h * B + b], acc);
    part[st * 64 + b] = acc;
    __syncthreads();
    if (st == 0)
        g_sc[s * B + b] = part[b] + part[64 + b] + part[128 + b] + part[192 + b];
}

__global__ void __launch_bounds__(256)
softmax_kernel(float* __restrict__ out) {
    __shared__ float s_red[8];
    int b = blockIdx.x, t = threadIdx.x;
    int lane = t & 31, warp = t >> 5;
    float v[2];
    v[0] = g_sc[t * B + b];
    v[1] = g_sc[(t + 256) * B + b];
    float m = fmaxf(v[0], v[1]);
    #pragma unroll
    for (int o = 16; o; o >>= 1) m = fmaxf(m, __shfl_xor_sync(~0u, m, o));
    if (lane == 0) s_red[warp] = m;
    __syncthreads();
    m = s_red[0];
    #pragma unroll
    for (int i = 1; i < 8; i++) m = fmaxf(m, s_red[i]);
    __syncthreads();
    float e0 = expf(v[0] - m), e1 = expf(v[1] - m);
    float sum = e0 + e1;
    #pragma unroll
    for (int o = 16; o; o >>= 1) sum += __shfl_xor_sync(~0u, sum, o);
    if (lane == 0) s_red[warp] = sum;
    __syncthreads();
    float tot = 0.0f;
    #pragma unroll
    for (int i = 0; i < 8; i++) tot += s_red[i];
    float inv = 1.0f / tot;
    float w0 = e0 * inv, w1 = e1 * inv;
    g_sc[t * B + b] = w0;
    g_sc[(t + 256) * B + b] = w1;
    out[NC * B + b * S + t] = w0;
    out[NC * B + b * S + t + 256] = w1;
}

__global__ void __launch_bounds__(256)
ctx_kernel() {
    __shared__ float part[4 * 64];
    int t = threadIdx.x, h = blockIdx.x;
    int st = t >> 6, b = t & 63;
    float acc = 0.0f;
    const float* Lb = g_lstm + (size_t)h * B + b;
    #pragma unroll 8
    for (int s = st * 128; s < st * 128 + 128; s++)
        acc = fmaf(g_sc[s * B + b], Lb[(size_t)s * H * B], acc);
    part[st * 64 + b] = acc;
    __syncthreads();
    if (st == 0)
        g_ctx[h * B + b] = part[b] + part[64 + b] + part[128 + b] + part[192 + b];
}

__global__ void __launch_bounds__(64)
fc_kernel(const float* __restrict__ fc_w, const float* __restrict__ fc_b,
          float* __restrict__ out) {
    __shared__ float wrow[H];
    int c = blockIdx.x, b = threadIdx.x;
    for (int i = b; i < H; i += 64) wrow[i] = fc_w[(size_t)c * H + i];
    __syncthreads();
    float acc = fc_b[c];
    #pragma unroll 8
    for (int h = 0; h < H; h++)
        acc = fmaf(wrow[h], g_ctx[h * B + b], acc);
    out[b * NC + c] = acc;
}

// ============================================================ launch
extern "C" void kernel_launch(void* const* d_in, const int* in_sizes, int n_in,
                              void* d_out, int out_size) {
    const float* x      = (const float*)d_in[0];
    const float* W_ih   = (const float*)d_in[1];
    const float* W_hh   = (const float*)d_in[2];
    const float* b_ih   = (const float*)d_in[3];
    const float* b_hh   = (const float*)d_in[4];
    const float* attn_w = (const float*)d_in[5];
    const float* fc_w   = (const float*)d_in[6];
    const float* fc_b   = (const float*)d_in[7];
    float* out = (float*)d_out;

    cudaFuncSetAttribute(lstm_kernel,
                         cudaFuncAttributeMaxDynamicSharedMemorySize, SMEM_BYTES);

    reset_kernel<<<260, 256>>>();
    prep_kernel<<<S, 64>>>(x);
    lstm_kernel<<<NCTA, NTH, SMEM_BYTES>>>(W_ih, W_hh, b_ih, b_hh);
    scores_kernel<<<S, 256>>>(attn_w);
    softmax_kernel<<<B, 256>>>(out);
    ctx_kernel<<<H, 256>>>();
    fc_kernel<<<NC, 64>>>(fc_w, fc_b, out);
}

// round 13
// speedup vs baseline: 1.6733x; 1.0361x over previous
#include <cuda_runtime.h>
#include <cuda_fp16.h>
#include <math.h>

#define B 64
#define S 512
#define H 512
#define IN 84
#define NC 100
#define XW 266

#define NGRP 4
#define GCTA 32
#define BPG 16
#define UPC 16
#define NCTA 128
#define NTH 256

// padded strides (halves): row stride ≡ odd*16 B mod 128 -> conflict-free ldmatrix
#define WST 648
#define XHST 520
#define XFST 136

#define INV256 0.00390625f

// ---- static device scratch ----
__device__ unsigned short g_hx[2 * NGRP * 16 * XHST];            // [par][grp][16b][520] fp16
__device__ unsigned short g_fx[(size_t)S * NGRP * 16 * XFST];    // [s][grp][16b][136] fp16
__device__ float g_lstm[(size_t)S * H * B];                      // [S][H][B]
__device__ float g_sc[S * B];
__device__ float g_ctx[H * B];
__device__ unsigned g_ctrs[64];

// ---- SMEM layout (bytes) ----
#define OFF_WHI   0                     // 64 x 648 fp16 = 82944
#define OFF_WLO   82944                 // Wlo * 256, fp16
#define OFF_XH    165888                // 16 x 520 fp16 = 16640
#define OFF_XF    182528                // 2 bufs x 16 x 136 fp16 = 8704
#define OFF_GSH   191232                // 2 planes x 64 x 17 f32 = 8704
#define OFF_HOUT  199936                // 16 x 17 f32
#define OFF_MB    201024                // 3 mbars
#define SMEM_BYTES 201056
#define XFBUF 4352                      // bytes per feats buffer
#define XHBYTES 16640                   // h plane bytes
#define GSHPL 1088                      // floats per gsh plane (64*17)

// ---- helpers ----
__device__ __forceinline__ unsigned smem_u32(const void* p) {
    return (unsigned)__cvta_generic_to_shared(p);
}
__device__ __forceinline__ void mbar_init(unsigned a, unsigned cnt) {
    asm volatile("mbarrier.init.shared.b64 [%0], %1;" :: "r"(a), "r"(cnt) : "memory");
}
__device__ __forceinline__ void mbar_expect(unsigned a, unsigned bytes) {
    asm volatile("mbarrier.arrive.expect_tx.shared.b64 _, [%0], %1;"
                 :: "r"(a), "r"(bytes) : "memory");
}
__device__ __forceinline__ void bulk_g2s(unsigned dst, const void* src,
                                         unsigned bytes, unsigned mbar) {
    asm volatile(
        "cp.async.bulk.shared::cluster.global.mbarrier::complete_tx::bytes "
        "[%0], [%1], %2, [%3];"
        :: "r"(dst), "l"(src), "r"(bytes), "r"(mbar) : "memory");
}
__device__ __forceinline__ void mbar_wait(unsigned a, unsigned parity) {
    asm volatile(
        "{\n\t.reg .pred P;\n\t"
        "W%=:\n\t"
        "mbarrier.try_wait.parity.shared.b64 P, [%0], %1, 0x989680;\n\t"
        "@P bra D%=;\n\t"
        "bra W%=;\n\t"
        "D%=:\n\t}"
        :: "r"(a), "r"(parity) : "memory");
}

#define LDSM4(r, addr) \
    asm volatile("ldmatrix.sync.aligned.m8n8.x4.shared.b16 {%0,%1,%2,%3}, [%4];" \
        : "=r"((r)[0]), "=r"((r)[1]), "=r"((r)[2]), "=r"((r)[3]) : "r"(addr))
#define MMAH16816(c, a, b0v, b1v) \
    asm volatile("mma.sync.aligned.m16n8k16.row.col.f32.f16.f16.f32 " \
        "{%0,%1,%2,%3}, {%4,%5,%6,%7}, {%8,%9}, {%0,%1,%2,%3};" \
        : "+f"((c)[0]), "+f"((c)[1]), "+f"((c)[2]), "+f"((c)[3]) \
        : "r"((a)[0]), "r"((a)[1]), "r"((a)[2]), "r"((a)[3]), "r"(b0v), "r"(b1v))

// one k-step: A hi + A lo(scaled) fragments, single-plane B; 2-pass into (cn, dn)
#define KSTEP2(aHI, aLO, bADDR) do {                      \
    unsigned ah[4], al[4], bh[4];                         \
    LDSM4(ah, aHI); LDSM4(al, aLO); LDSM4(bh, bADDR);     \
    MMAH16816(cn0, ah, bh[0], bh[1]);                     \
    MMAH16816(cn1, ah, bh[2], bh[3]);                     \
    MMAH16816(dn0, al, bh[0], bh[1]);                     \
    MMAH16816(dn1, al, bh[2], bh[3]);                     \
} while (0)

__device__ __forceinline__ float sigf(float x) {
    return __fdividef(1.0f, 1.0f + __expf(-x));
}
__device__ __forceinline__ float tanhfast(float x) {
    return __fdividef(2.0f, 1.0f + __expf(-2.0f * x)) - 1.0f;
}
__device__ __forceinline__ unsigned short f16r(float v) {
    __half h = __float2half_rn(v);
    unsigned short r; memcpy(&r, &h, 2); return r;
}

// ============================================================ reset
__global__ void reset_kernel() {
    int t = blockIdx.x * blockDim.x + threadIdx.x;
    if (t < 64) g_ctrs[t] = 0u;
    if (t < (int)(sizeof(g_hx) / 4)) ((unsigned*)g_hx)[t] = 0u;
}

// ============================================================ preprocessing
__global__ void prep_kernel(const float* __restrict__ x) {
    int s = blockIdx.x;
    int b = threadIdx.x;                 // 64 threads
    int grp = b >> 4, bl = b & 15;
    unsigned short* fh = g_fx + ((size_t)s * NGRP + grp) * 16 * XFST + bl * XFST;
    #pragma unroll 4
    for (int c = 0; c < XFST; c++) fh[c] = 0;

    const float* xp = x + ((size_t)b * S + s) * XW;
    float cx = xp[0], cy = xp[1];
    #pragma unroll
    for (int hnd = 0; hnd < 2; hnd++) {
        int pbase = (hnd == 0) ? 91 : 112;
        float mnx = 1e30f, mxx = -1e30f, mny = 1e30f, mxy = -1e30f;
        #pragma unroll
        for (int p = 0; p < 21; p++) {
            float px = xp[(pbase + p) * 2];
            float py = xp[(pbase + p) * 2 + 1];
            mnx = fminf(mnx, px); mxx = fmaxf(mxx, px);
            mny = fminf(mny, py); mxy = fmaxf(mxy, py);
        }
        float whx = mxx - mnx, why = mxy - mny;
        bool ok = (whx != 0.0f) && (why != 0.0f);
        float sx = ok ? whx : 1.0f;
        float sy = ok ? why : 1.0f;
        #pragma unroll
        for (int p = 0; p < 21; p++) {
            float px = (xp[(pbase + p) * 2] - cx) / sx;
            float py = (xp[(pbase + p) * 2 + 1] - cy) / sy;
            int i0 = hnd * 42 + p * 2;
            fh[i0]     = f16r(px);
            fh[i0 + 1] = f16r(py);
        }
    }
    fh[84] = f16r(1.0f);   // bias row
}

// ============================================================ recurrence (fp16 HMMA, 8-warp K-split)
__global__ void __launch_bounds__(NTH, 1)
lstm_kernel(const float* __restrict__ W_ih, const float* __restrict__ W_hh,
            const float* __restrict__ b_ih, const float* __restrict__ b_hh) {
    extern __shared__ char smc[];
    const int t = threadIdx.x;
    const int blk = blockIdx.x;
    const int grp = blk >> 5;
    const int cg = blk & 31;
    const int lane = t & 31;
    const int wid = t >> 5;
    const int wg = wid >> 2;             // 0/1: K-split group
    const unsigned sbase = smem_u32(smc);

    // ---- one-time W staging: fp16 hi + scaled lo, [64 rows][648 cols] (cols < 608 live) ----
    for (int idx = t; idx < 64 * 608; idx += NTH) {
        int r = idx & 63, k = idx >> 6;
        int grow = (r >> 4) * H + cg * UPC + (r & 15);
        float w;
        if (k < 512)        w = W_hh[(size_t)grow * H + k];
        else if (k < 596)   w = W_ih[(size_t)grow * IN + (k - 512)];
        else if (k == 596)  w = b_ih[grow] + b_hh[grow];
        else                w = 0.0f;
        __half hi = __float2half_rn(w);
        __half lo = __float2half_rn((w - __half2float(hi)) * 256.0f);
        ((__half*)(smc + OFF_WHI))[r * WST + k] = hi;
        ((__half*)(smc + OFF_WLO))[r * WST + k] = lo;
    }
    if (t == 0) {
        mbar_init(sbase + OFF_MB + 0, 1);    // h
        mbar_init(sbase + OFF_MB + 8, 1);    // feats buf0
        mbar_init(sbase + OFF_MB + 16, 1);   // feats buf1
    }
    __syncthreads();

    const unsigned mbh = sbase + OFF_MB;
    const unsigned mbf = sbase + OFF_MB + 8;

    // ldmatrix per-lane addresses
    const unsigned aA = (unsigned)(((wid & 3) * 16 + (lane & 15)) * WST + (lane >> 4) * 8) * 2;
    const unsigned aAhi = sbase + OFF_WHI + aA;
    const unsigned aAlo = sbase + OFF_WLO + aA;
    // B non-trans from [n][k] storage:
    //  lanes 0-7: n0-7,k+0 | 8-15: n0-7,k+8 | 16-23: n8-15,k+0 | 24-31: n8-15,k+8
    const unsigned nrow = (lane & 7) + ((lane >> 4) & 1) * 8;
    const unsigned kofs = ((lane >> 3) & 1) * 8;
    const unsigned aBh = sbase + OFF_XH + (unsigned)(nrow * XHST + kofs) * 2;
    const unsigned aBf = (unsigned)(nrow * XFST + kofs) * 2;

    // gate mapping
    const int ul = t & 15, gb = t >> 4;
    const int u_glob = cg * UPC + ul;
    float creg = 0.0f;

    float* gsh  = (float*)(smc + OFF_GSH);        // plane 0
    float* gsh1 = gsh + GSHPL;                    // plane 1
    float* hout = (float*)(smc + OFF_HOUT);
    unsigned* my_ctr = &g_ctrs[grp * 16];
    const unsigned short* hsrc_base = g_hx + (size_t)grp * 16 * XHST;
    const unsigned short* fsrc_base = g_fx + (size_t)grp * 16 * XFST;

    float* gshp = gsh + wg * GSHPL;               // this warp-group's output plane

    // prefetch feats s=0 into buf 0
    if (t == 0) {
        asm volatile("fence.proxy.async;" ::: "memory");
        mbar_expect(mbf, XFBUF);
        bulk_g2s(sbase + OFF_XF, fsrc_base, XFBUF, mbf);
    }

    for (int s = 0; s < S; s++) {
        const int cur = s & 1, nxt = cur ^ 1;
        const unsigned par = (unsigned)(s & 1);
        const int fb = s & 1;
        const unsigned fpar = (unsigned)((s >> 1) & 1);

        // ---- t0 issues h copy + feats prefetch for s+1 ----
        if (t == 0) {
            asm volatile("fence.proxy.async;" ::: "memory");
            mbar_expect(mbh, XHBYTES);
            bulk_g2s(sbase + OFF_XH,
                     hsrc_base + (size_t)cur * NGRP * 16 * XHST,
                     XHBYTES, mbh);
            if (s + 1 < S) {
                int nb = (s + 1) & 1;
                mbar_expect(mbf + nb * 8, XFBUF);
                bulk_g2s(sbase + OFF_XF + (unsigned)nb * XFBUF,
                         fsrc_base + (size_t)(s + 1) * NGRP * 16 * XFST,
                         XFBUF, mbf + nb * 8);
            }
        }

        {
            float cn0[4] = {0, 0, 0, 0};
            float cn1[4] = {0, 0, 0, 0};
            float dn0[4] = {0, 0, 0, 0};
            float dn1[4] = {0, 0, 0, 0};

            // ---- feats k-steps (3 per group; W cols 512..607) ----
            mbar_wait(mbf + fb * 8, fpar);
            {
                const unsigned fba = sbase + OFF_XF + (unsigned)fb * XFBUF + aBf;
                #pragma unroll
                for (int j = 0; j < 3; j++) {
                    int jg = wg * 3 + j;
                    KSTEP2(aAhi + 1024 + jg * 32, aAlo + 1024 + jg * 32,
                           fba + jg * 32);
                }
            }
            // ---- h k-steps (16 per group; W cols 0..511) ----
            mbar_wait(mbh, par);
            #pragma unroll 4
            for (int j = 0; j < 16; j++) {
                int jg = wg * 16 + j;
                KSTEP2(aAhi + jg * 32, aAlo + jg * 32, aBh + jg * 32);
            }

            // ---- combine passes + D writeback to own gsh plane ----
            {
                int r0 = (wid & 3) * 16 + (lane >> 2);
                int c0 = (lane & 3) * 2;
                gshp[r0 * 17 + c0]           = cn0[0] + dn0[0] * INV256;
                gshp[r0 * 17 + c0 + 1]       = cn0[1] + dn0[1] * INV256;
                gshp[(r0 + 8) * 17 + c0]     = cn0[2] + dn0[2] * INV256;
                gshp[(r0 + 8) * 17 + c0 + 1] = cn0[3] + dn0[3] * INV256;
                gshp[r0 * 17 + 8 + c0]           = cn1[0] + dn1[0] * INV256;
                gshp[r0 * 17 + 8 + c0 + 1]       = cn1[1] + dn1[1] * INV256;
                gshp[(r0 + 8) * 17 + 8 + c0]     = cn1[2] + dn1[2] * INV256;
                gshp[(r0 + 8) * 17 + 8 + c0 + 1] = cn1[3] + dn1[3] * INV256;
            }
        }
        __syncthreads();

        // ---- gates: thread = (unit ul, batch gb); sum the two K-split planes ----
        {
            float gi = gsh[(0 * 16 + ul) * 17 + gb] + gsh1[(0 * 16 + ul) * 17 + gb];
            float gf = gsh[(1 * 16 + ul) * 17 + gb] + gsh1[(1 * 16 + ul) * 17 + gb];
            float gg = gsh[(2 * 16 + ul) * 17 + gb] + gsh1[(2 * 16 + ul) * 17 + gb];
            float go = gsh[(3 * 16 + ul) * 17 + gb] + gsh1[(3 * 16 + ul) * 17 + gb];
            float i_ = sigf(gi), f_ = sigf(gf);
            float g_ = tanhfast(gg), o_ = sigf(go);
            creg = f_ * creg + i_ * g_;
            float hn = o_ * tanhfast(creg);
            size_t hbase = (size_t)(nxt * NGRP + grp) * 16 * XHST;
            g_hx[hbase + gb * XHST + u_glob] = f16r(hn);
            hout[ul * 17 + gb] = hn;
        }
        __syncthreads();
        {
            int u2 = t >> 4, b2 = t & 15;
            g_lstm[((size_t)s * H + cg * UPC + u2) * B + grp * BPG + b2] =
                hout[u2 * 17 + b2];
        }

        // ---- group barrier ----
        if (s != S - 1) {
            if (t == 0) {
                asm volatile("red.add.release.gpu.u32 [%0], %1;"
                             :: "l"(my_ctr), "r"(1u) : "memory");
                unsigned target = (unsigned)(s + 1) * GCTA;
                unsigned v;
                do {
                    asm volatile("ld.acquire.gpu.u32 %0, [%1];"
                                 : "=r"(v) : "l"(my_ctr) : "memory");
                } while (v < target);
            }
            __syncthreads();
        }
    }
}

// ============================================================ attention
__global__ void __launch_bounds__(256)
scores_kernel(const float* __restrict__ attn_w) {
    __shared__ float aw[H];
    __shared__ float part[4 * 64];
    int t = threadIdx.x, s = blockIdx.x;
    int st = t >> 6, b = t & 63;
    for (int i = t; i < H; i += 256) aw[i] = attn_w[i];
    __syncthreads();
    const float* Ls = g_lstm + (size_t)s * H * B;
    float acc = 0.0f;
    #pragma unroll 8
    for (int h = st * 128; h < st * 128 + 128; h++)
        acc = fmaf(aw[h], Ls[h * B + b], acc);
    part[st * 64 + b] = acc;
    __syncthreads();
    if (st == 0)
        g_sc[s * B + b] = part[b] + part[64 + b] + part[128 + b] + part[192 + b];
}

__global__ void __launch_bounds__(256)
softmax_kernel(float* __restrict__ out) {
    __shared__ float s_red[8];
    int b = blockIdx.x, t = threadIdx.x;
    int lane = t & 31, warp = t >> 5;
    float v[2];
    v[0] = g_sc[t * B + b];
    v[1] = g_sc[(t + 256) * B + b];
    float m = fmaxf(v[0], v[1]);
    #pragma unroll
    for (int o = 16; o; o >>= 1) m = fmaxf(m, __shfl_xor_sync(~0u, m, o));
    if (lane == 0) s_red[warp] = m;
    __syncthreads();
    m = s_red[0];
    #pragma unroll
    for (int i = 1; i < 8; i++) m = fmaxf(m, s_red[i]);
    __syncthreads();
    float e0 = expf(v[0] - m), e1 = expf(v[1] - m);
    float sum = e0 + e1;
    #pragma unroll
    for (int o = 16; o; o >>= 1) sum += __shfl_xor_sync(~0u, sum, o);
    if (lane == 0) s_red[warp] = sum;
    __syncthreads();
    float tot = 0.0f;
    #pragma unroll
    for (int i = 0; i < 8; i++) tot += s_red[i];
    float inv = 1.0f / tot;
    float w0 = e0 * inv, w1 = e1 * inv;
    g_sc[t * B + b] = w0;
    g_sc[(t + 256) * B + b] = w1;
    out[NC * B + b * S + t] = w0;
    out[NC * B + b * S + t + 256] = w1;
}

__global__ void __launch_bounds__(256)
ctx_kernel() {
    __shared__ float part[4 * 64];
    int t = threadIdx.x, h = blockIdx.x;
    int st = t >> 6, b = t & 63;
    float acc = 0.0f;
    const float* Lb = g_lstm + (size_t)h * B + b;
    #pragma unroll 8
    for (int s = st * 128; s < st * 128 + 128; s++)
        acc = fmaf(g_sc[s * B + b], Lb[(size_t)s * H * B], acc);
    part[st * 64 + b] = acc;
    __syncthreads();
    if (st == 0)
        g_ctx[h * B + b] = part[b] + part[64 + b] + part[128 + b] + part[192 + b];
}

__global__ void __launch_bounds__(64)
fc_kernel(const float* __restrict__ fc_w, const float* __restrict__ fc_b,
          float* __restrict__ out) {
    __shared__ float wrow[H];
    int c = blockIdx.x, b = threadIdx.x;
    for (int i = b; i < H; i += 64) wrow[i] = fc_w[(size_t)c * H + i];
    __syncthreads();
    float acc = fc_b[c];
    #pragma unroll 8
    for (int h = 0; h < H; h++)
        acc = fmaf(wrow[h], g_ctx[h * B + b], acc);
    out[b * NC + c] = acc;
}

// ============================================================ launch
extern "C" void kernel_launch(void* const* d_in, const int* in_sizes, int n_in,
                              void* d_out, int out_size) {
    const float* x      = (const float*)d_in[0];
    const float* W_ih   = (const float*)d_in[1];
    const float* W_hh   = (const float*)d_in[2];
    const float* b_ih   = (const float*)d_in[3];
    const float* b_hh   = (const float*)d_in[4];
    const float* attn_w = (const float*)d_in[5];
    const float* fc_w   = (const float*)d_in[6];
    const float* fc_b   = (const float*)d_in[7];
    float* out = (float*)d_out;

    cudaFuncSetAttribute(lstm_kernel,
                         cudaFuncAttributeMaxDynamicSharedMemorySize, SMEM_BYTES);

    reset_kernel<<<260, 256>>>();
    prep_kernel<<<S, 64>>>(x);
    lstm_kernel<<<NCTA, NTH, SMEM_BYTES>>>(W_ih, W_hh, b_ih, b_hh);
    scores_kernel<<<S, 256>>>(attn_w);
    softmax_kernel<<<B, 256>>>(out);
    ctx_kernel<<<H, 256>>>();
    fc_kernel<<<NC, 64>>>(fc_w, fc_b, out);
}

// round 14
// speedup vs baseline: 1.8928x; 1.1312x over previous
#include <cuda_runtime.h>
#include <cuda_fp16.h>
#include <math.h>

#define B 64
#define S 512
#define H 512
#define IN 84
#define NC 100
#define XW 266

#define NGRP 4
#define GCTA 32
#define BPG 16
#define UPC 16
#define NCTA 128
#define NTH 256

// padded strides (halves): row stride ≡ odd*16 B mod 128 -> conflict-free ldmatrix
#define WST 648
#define XHST 520
#define XFST 136

// ---- static device scratch ----
__device__ unsigned short g_hx[2 * NGRP * 16 * XHST];            // [par][grp][16b][520] fp16
__device__ unsigned short g_fx[(size_t)S * NGRP * 16 * XFST];    // [s][grp][16b][136] fp16
__device__ float g_lstm[(size_t)S * H * B];                      // [S][H][B]
__device__ float g_sc[S * B];
__device__ float g_ctx[H * B];
__device__ unsigned g_ctrs[64];

// ---- SMEM layout (bytes) ----
#define OFF_WHI   0                     // 64 x 648 fp16 = 82944
#define OFF_XH    82944                 // 16 x 520 fp16 = 16640
#define OFF_XF    99584                 // 2 bufs x 16 x 136 fp16 = 8704
#define OFF_GSH   108288                // 2 planes x 64 x 17 f32 = 8704
#define OFF_HOUT  116992                // 16 x 17 f32
#define OFF_MB    118080                // 3 mbars
#define SMEM_BYTES 118112
#define XFBUF 4352                      // bytes per feats buffer
#define XHBYTES 16640                   // h plane bytes
#define GSHPL 1088                      // floats per gsh plane (64*17)

// ---- helpers ----
__device__ __forceinline__ unsigned smem_u32(const void* p) {
    return (unsigned)__cvta_generic_to_shared(p);
}
__device__ __forceinline__ void mbar_init(unsigned a, unsigned cnt) {
    asm volatile("mbarrier.init.shared.b64 [%0], %1;" :: "r"(a), "r"(cnt) : "memory");
}
__device__ __forceinline__ void mbar_expect(unsigned a, unsigned bytes) {
    asm volatile("mbarrier.arrive.expect_tx.shared.b64 _, [%0], %1;"
                 :: "r"(a), "r"(bytes) : "memory");
}
__device__ __forceinline__ void bulk_g2s(unsigned dst, const void* src,
                                         unsigned bytes, unsigned mbar) {
    asm volatile(
        "cp.async.bulk.shared::cluster.global.mbarrier::complete_tx::bytes "
        "[%0], [%1], %2, [%3];"
        :: "r"(dst), "l"(src), "r"(bytes), "r"(mbar) : "memory");
}
__device__ __forceinline__ void mbar_wait(unsigned a, unsigned parity) {
    asm volatile(
        "{\n\t.reg .pred P;\n\t"
        "W%=:\n\t"
        "mbarrier.try_wait.parity.shared.b64 P, [%0], %1, 0x989680;\n\t"
        "@P bra D%=;\n\t"
        "bra W%=;\n\t"
        "D%=:\n\t}"
        :: "r"(a), "r"(parity) : "memory");
}

#define LDSM4(r, addr) \
    asm volatile("ldmatrix.sync.aligned.m8n8.x4.shared.b16 {%0,%1,%2,%3}, [%4];" \
        : "=r"((r)[0]), "=r"((r)[1]), "=r"((r)[2]), "=r"((r)[3]) : "r"(addr))
#define MMAH16816(c, a, b0v, b1v) \
    asm volatile("mma.sync.aligned.m16n8k16.row.col.f32.f16.f16.f32 " \
        "{%0,%1,%2,%3}, {%4,%5,%6,%7}, {%8,%9}, {%0,%1,%2,%3};" \
        : "+f"((c)[0]), "+f"((c)[1]), "+f"((c)[2]), "+f"((c)[3]) \
        : "r"((a)[0]), "r"((a)[1]), "r"((a)[2]), "r"((a)[3]), "r"(b0v), "r"(b1v))

// one k-step, single-pass W: A hi fragment, B fragment; 2 MMA into (cn0, cn1)
#define KSTEP1(aHI, bADDR) do {                           \
    unsigned ah[4], bh[4];                                \
    LDSM4(ah, aHI); LDSM4(bh, bADDR);                     \
    MMAH16816(cn0, ah, bh[0], bh[1]);                     \
    MMAH16816(cn1, ah, bh[2], bh[3]);                     \
} while (0)
// feats variant accumulating into carry registers (fcn0, fcn1)
#define KSTEPF(aHI, bADDR) do {                           \
    unsigned ah[4], bh[4];                                \
    LDSM4(ah, aHI); LDSM4(bh, bADDR);                     \
    MMAH16816(fcn0, ah, bh[0], bh[1]);                    \
    MMAH16816(fcn1, ah, bh[2], bh[3]);                    \
} while (0)

__device__ __forceinline__ float sigf(float x) {
    return __fdividef(1.0f, 1.0f + __expf(-x));
}
__device__ __forceinline__ float tanhfast(float x) {
    return __fdividef(2.0f, 1.0f + __expf(-2.0f * x)) - 1.0f;
}
__device__ __forceinline__ unsigned short f16r(float v) {
    __half h = __float2half_rn(v);
    unsigned short r; memcpy(&r, &h, 2); return r;
}

// ============================================================ reset
__global__ void reset_kernel() {
    int t = blockIdx.x * blockDim.x + threadIdx.x;
    if (t < 64) g_ctrs[t] = 0u;
    if (t < (int)(sizeof(g_hx) / 4)) ((unsigned*)g_hx)[t] = 0u;
}

// ============================================================ preprocessing
__global__ void prep_kernel(const float* __restrict__ x) {
    int s = blockIdx.x;
    int b = threadIdx.x;                 // 64 threads
    int grp = b >> 4, bl = b & 15;
    unsigned short* fh = g_fx + ((size_t)s * NGRP + grp) * 16 * XFST + bl * XFST;
    #pragma unroll 4
    for (int c = 0; c < XFST; c++) fh[c] = 0;

    const float* xp = x + ((size_t)b * S + s) * XW;
    float cx = xp[0], cy = xp[1];
    #pragma unroll
    for (int hnd = 0; hnd < 2; hnd++) {
        int pbase = (hnd == 0) ? 91 : 112;
        float mnx = 1e30f, mxx = -1e30f, mny = 1e30f, mxy = -1e30f;
        #pragma unroll
        for (int p = 0; p < 21; p++) {
            float px = xp[(pbase + p) * 2];
            float py = xp[(pbase + p) * 2 + 1];
            mnx = fminf(mnx, px); mxx = fmaxf(mxx, px);
            mny = fminf(mny, py); mxy = fmaxf(mxy, py);
        }
        float whx = mxx - mnx, why = mxy - mny;
        bool ok = (whx != 0.0f) && (why != 0.0f);
        float sx = ok ? whx : 1.0f;
        float sy = ok ? why : 1.0f;
        #pragma unroll
        for (int p = 0; p < 21; p++) {
            float px = (xp[(pbase + p) * 2] - cx) / sx;
            float py = (xp[(pbase + p) * 2 + 1] - cy) / sy;
            int i0 = hnd * 42 + p * 2;
            fh[i0]     = f16r(px);
            fh[i0 + 1] = f16r(py);
        }
    }
    fh[84] = f16r(1.0f);   // bias row
}

// ============================================================ recurrence (fp16 HMMA 1-pass, pipelined feats)
__global__ void __launch_bounds__(NTH, 1)
lstm_kernel(const float* __restrict__ W_ih, const float* __restrict__ W_hh,
            const float* __restrict__ b_ih, const float* __restrict__ b_hh) {
    extern __shared__ char smc[];
    const int t = threadIdx.x;
    const int blk = blockIdx.x;
    const int grp = blk >> 5;
    const int cg = blk & 31;
    const int lane = t & 31;
    const int wid = t >> 5;
    const int wg = wid >> 2;             // 0/1: K-split group
    const unsigned sbase = smem_u32(smc);

    // ---- one-time W staging: fp16, [64 rows][648 cols] (cols < 608 live) ----
    for (int idx = t; idx < 64 * 608; idx += NTH) {
        int r = idx & 63, k = idx >> 6;
        int grow = (r >> 4) * H + cg * UPC + (r & 15);
        float w;
        if (k < 512)        w = W_hh[(size_t)grow * H + k];
        else if (k < 596)   w = W_ih[(size_t)grow * IN + (k - 512)];
        else if (k == 596)  w = b_ih[grow] + b_hh[grow];
        else                w = 0.0f;
        ((__half*)(smc + OFF_WHI))[r * WST + k] = __float2half_rn(w);
    }
    if (t == 0) {
        mbar_init(sbase + OFF_MB + 0, 1);    // h
        mbar_init(sbase + OFF_MB + 8, 1);    // feats buf0
        mbar_init(sbase + OFF_MB + 16, 1);   // feats buf1
    }
    __syncthreads();

    const unsigned mbh = sbase + OFF_MB;
    const unsigned mbf = sbase + OFF_MB + 8;

    // ldmatrix per-lane addresses
    const unsigned aA = (unsigned)(((wid & 3) * 16 + (lane & 15)) * WST + (lane >> 4) * 8) * 2;
    const unsigned aAhi = sbase + OFF_WHI + aA;
    // B non-trans from [n][k] storage:
    //  lanes 0-7: n0-7,k+0 | 8-15: n0-7,k+8 | 16-23: n8-15,k+0 | 24-31: n8-15,k+8
    const unsigned nrow = (lane & 7) + ((lane >> 4) & 1) * 8;
    const unsigned kofs = ((lane >> 3) & 1) * 8;
    const unsigned aBh = sbase + OFF_XH + (unsigned)(nrow * XHST + kofs) * 2;
    const unsigned aBf = (unsigned)(nrow * XFST + kofs) * 2;

    // gate mapping
    const int ul = t & 15, gb = t >> 4;
    const int u_glob = cg * UPC + ul;
    float creg = 0.0f;

    float* gsh  = (float*)(smc + OFF_GSH);        // plane 0
    float* gsh1 = gsh + GSHPL;                    // plane 1
    float* hout = (float*)(smc + OFF_HOUT);
    unsigned* my_ctr = &g_ctrs[grp * 16];
    const unsigned short* hsrc_base = g_hx + (size_t)grp * 16 * XHST;
    const unsigned short* fsrc_base = g_fx + (size_t)grp * 16 * XFST;

    float* gshp = gsh + wg * GSHPL;               // this warp-group's output plane

    // prefetch feats s=0 into buf 0
    if (t == 0) {
        asm volatile("fence.proxy.async;" ::: "memory");
        mbar_expect(mbf, XFBUF);
        bulk_g2s(sbase + OFF_XF, fsrc_base, XFBUF, mbf);
    }

    // feats carry accumulators: hold the feats+bias contribution for step s
    float fcn0[4] = {0, 0, 0, 0};
    float fcn1[4] = {0, 0, 0, 0};

    // preloop: feats MMA for s = 0 (buf 0, parity 0)
    mbar_wait(mbf, 0);
    {
        const unsigned fba = sbase + OFF_XF + aBf;
        #pragma unroll
        for (int j = 0; j < 3; j++) {
            int jg = wg * 3 + j;
            KSTEPF(aAhi + 1024 + jg * 32, fba + jg * 32);
        }
    }

    for (int s = 0; s < S; s++) {
        const int cur = s & 1, nxt = cur ^ 1;
        const unsigned par = (unsigned)(s & 1);

        // ---- t0 issues h copy (for s) + feats prefetch for s+1 ----
        if (t == 0) {
            asm volatile("fence.proxy.async;" ::: "memory");
            mbar_expect(mbh, XHBYTES);
            bulk_g2s(sbase + OFF_XH,
                     hsrc_base + (size_t)cur * NGRP * 16 * XHST,
                     XHBYTES, mbh);
            if (s + 1 < S) {
                int nb = (s + 1) & 1;
                mbar_expect(mbf + nb * 8, XFBUF);
                bulk_g2s(sbase + OFF_XF + (unsigned)nb * XFBUF,
                         fsrc_base + (size_t)(s + 1) * NGRP * 16 * XFST,
                         XFBUF, mbf + nb * 8);
            }
        }

        {
            float cn0[4] = {fcn0[0], fcn0[1], fcn0[2], fcn0[3]};
            float cn1[4] = {fcn1[0], fcn1[1], fcn1[2], fcn1[3]};

            // ---- h k-steps (16 per K-split group; W cols 0..511) ----
            mbar_wait(mbh, par);
            #pragma unroll 4
            for (int j = 0; j < 16; j++) {
                int jg = wg * 16 + j;
                KSTEP1(aAhi + jg * 32, aBh + jg * 32);
            }

            // ---- D writeback to own gsh plane ----
            {
                int r0 = (wid & 3) * 16 + (lane >> 2);
                int c0 = (lane & 3) * 2;
                gshp[r0 * 17 + c0]           = cn0[0];
                gshp[r0 * 17 + c0 + 1]       = cn0[1];
                gshp[(r0 + 8) * 17 + c0]     = cn0[2];
                gshp[(r0 + 8) * 17 + c0 + 1] = cn0[3];
                gshp[r0 * 17 + 8 + c0]           = cn1[0];
                gshp[r0 * 17 + 8 + c0 + 1]       = cn1[1];
                gshp[(r0 + 8) * 17 + 8 + c0]     = cn1[2];
                gshp[(r0 + 8) * 17 + 8 + c0 + 1] = cn1[3];
            }
        }
        __syncthreads();

        // ---- gates: thread = (unit ul, batch gb); sum the two K-split planes ----
        {
            float gi = gsh[(0 * 16 + ul) * 17 + gb] + gsh1[(0 * 16 + ul) * 17 + gb];
            float gf = gsh[(1 * 16 + ul) * 17 + gb] + gsh1[(1 * 16 + ul) * 17 + gb];
            float gg = gsh[(2 * 16 + ul) * 17 + gb] + gsh1[(2 * 16 + ul) * 17 + gb];
            float go = gsh[(3 * 16 + ul) * 17 + gb] + gsh1[(3 * 16 + ul) * 17 + gb];
            float i_ = sigf(gi), f_ = sigf(gf);
            float g_ = tanhfast(gg), o_ = sigf(go);
            creg = f_ * creg + i_ * g_;
            float hn = o_ * tanhfast(creg);
            size_t hbase = (size_t)(nxt * NGRP + grp) * 16 * XHST;
            g_hx[hbase + gb * XHST + u_glob] = f16r(hn);
            hout[ul * 17 + gb] = hn;
        }
        __syncthreads();
        {
            int u2 = t >> 4, b2 = t & 15;
            g_lstm[((size_t)s * H + cg * UPC + u2) * B + grp * BPG + b2] =
                hout[u2 * 17 + b2];
        }

        // ---- tail: arrive, then hide next-step feats MMA under barrier drain ----
        if (s != S - 1) {
            if (t == 0) {
                asm volatile("red.add.release.gpu.u32 [%0], %1;"
                             :: "l"(my_ctr), "r"(1u) : "memory");
            }
            // feats MMA for s+1 (prefetched; independent of the barrier)
            {
                const int fb2 = (s + 1) & 1;
                const unsigned fpar2 = (unsigned)(((s + 1) >> 1) & 1);
                mbar_wait(mbf + fb2 * 8, fpar2);
                fcn0[0] = fcn0[1] = fcn0[2] = fcn0[3] = 0.0f;
                fcn1[0] = fcn1[1] = fcn1[2] = fcn1[3] = 0.0f;
                const unsigned fba = sbase + OFF_XF + (unsigned)fb2 * XFBUF + aBf;
                #pragma unroll
                for (int j = 0; j < 3; j++) {
                    int jg = wg * 3 + j;
                    KSTEPF(aAhi + 1024 + jg * 32, fba + jg * 32);
                }
            }
            if (t == 0) {
                unsigned target = (unsigned)(s + 1) * GCTA;
                unsigned v;
                do {
                    asm volatile("ld.acquire.gpu.u32 %0, [%1];"
                                 : "=r"(v) : "l"(my_ctr) : "memory");
                } while (v < target);
            }
            __syncthreads();
        }
    }
}

// ============================================================ attention
__global__ void __launch_bounds__(256)
scores_kernel(const float* __restrict__ attn_w) {
    __shared__ float aw[H];
    __shared__ float part[4 * 64];
    int t = threadIdx.x, s = blockIdx.x;
    int st = t >> 6, b = t & 63;
    for (int i = t; i < H; i += 256) aw[i] = attn_w[i];
    __syncthreads();
    const float* Ls = g_lstm + (size_t)s * H * B;
    float acc = 0.0f;
    #pragma unroll 8
    for (int h = st * 128; h < st * 128 + 128; h++)
        acc = fmaf(aw[h], Ls[h * B + b], acc);
    part[st * 64 + b] = acc;
    __syncthreads();
    if (st == 0)
        g_sc[s * B + b] = part[b] + part[64 + b] + part[128 + b] + part[192 + b];
}

__global__ void __launch_bounds__(256)
softmax_kernel(float* __restrict__ out) {
    __shared__ float s_red[8];
    int b = blockIdx.x, t = threadIdx.x;
    int lane = t & 31, warp = t >> 5;
    float v[2];
    v[0] = g_sc[t * B + b];
    v[1] = g_sc[(t + 256) * B + b];
    float m = fmaxf(v[0], v[1]);
    #pragma unroll
    for (int o = 16; o; o >>= 1) m = fmaxf(m, __shfl_xor_sync(~0u, m, o));
    if (lane == 0) s_red[warp] = m;
    __syncthreads();
    m = s_red[0];
    #pragma unroll
    for (int i = 1; i < 8; i++) m = fmaxf(m, s_red[i]);
    __syncthreads();
    float e0 = expf(v[0] - m), e1 = expf(v[1] - m);
    float sum = e0 + e1;
    #pragma unroll
    for (int o = 16; o; o >>= 1) sum += __shfl_xor_sync(~0u, sum, o);
    if (lane == 0) s_red[warp] = sum;
    __syncthreads();
    float tot = 0.0f;
    #pragma unroll
    for (int i = 0; i < 8; i++) tot += s_red[i];
    float inv = 1.0f / tot;
    float w0 = e0 * inv, w1 = e1 * inv;
    g_sc[t * B + b] = w0;
    g_sc[(t + 256) * B + b] = w1;
    out[NC * B + b * S + t] = w0;
    out[NC * B + b * S + t + 256] = w1;
}

__global__ void __launch_bounds__(256)
ctx_kernel() {
    __shared__ float part[4 * 64];
    int t = threadIdx.x, h = blockIdx.x;
    int st = t >> 6, b = t & 63;
    float acc = 0.0f;
    const float* Lb = g_lstm + (size_t)h * B + b;
    #pragma unroll 8
    for (int s = st * 128; s < st * 128 + 128; s++)
        acc = fmaf(g_sc[s * B + b], Lb[(size_t)s * H * B], acc);
    part[st * 64 + b] = acc;
    __syncthreads();
    if (st == 0)
        g_ctx[h * B + b] = part[b] + part[64 + b] + part[128 + b] + part[192 + b];
}

__global__ void __launch_bounds__(64)
fc_kernel(const float* __restrict__ fc_w, const float* __restrict__ fc_b,
          float* __restrict__ out) {
    __shared__ float wrow[H];
    int c = blockIdx.x, b = threadIdx.x;
    for (int i = b; i < H; i += 64) wrow[i] = fc_w[(size_t)c * H + i];
    __syncthreads();
    float acc = fc_b[c];
    #pragma unroll 8
    for (int h = 0; h < H; h++)
        acc = fmaf(wrow[h], g_ctx[h * B + b], acc);
    out[b * NC + c] = acc;
}

// ============================================================ launch
extern "C" void kernel_launch(void* const* d_in, const int* in_sizes, int n_in,
                              void* d_out, int out_size) {
    const float* x      = (const float*)d_in[0];
    const float* W_ih   = (const float*)d_in[1];
    const float* W_hh   = (const float*)d_in[2];
    const float* b_ih   = (const float*)d_in[3];
    const float* b_hh   = (const float*)d_in[4];
    const float* attn_w = (const float*)d_in[5];
    const float* fc_w   = (const float*)d_in[6];
    const float* fc_b   = (const float*)d_in[7];
    float* out = (float*)d_out;

    cudaFuncSetAttribute(lstm_kernel,
                         cudaFuncAttributeMaxDynamicSharedMemorySize, SMEM_BYTES);

    reset_kernel<<<260, 256>>>();
    prep_kernel<<<S, 64>>>(x);
    lstm_kernel<<<NCTA, NTH, SMEM_BYTES>>>(W_ih, W_hh, b_ih, b_hh);
    scores_kernel<<<S, 256>>>(attn_w);
    softmax_kernel<<<B, 256>>>(out);
    ctx_kernel<<<H, 256>>>();
    fc_kernel<<<NC, 64>>>(fc_w, fc_b, out);
}